// round 5
// baseline (speedup 1.0000x reference)
#include <cuda_runtime.h>
#include <math.h>

// ---------------- problem constants ----------------
#define NN 100000
#define NC 50000
#define EE 400000
#define ND 43
#define CD 2
#define HID 128
#define NL 4
#define SLOPE 0.2f
#define LNEPS 1e-5f

#define SCHUNK 2048
#define NB_M ((NC + SCHUNK - 1) / SCHUNK)   // 25
#define NB_C ((NN + SCHUNK - 1) / SCHUNK)   // 49
#define NB_T (NB_M + NB_C)                  // 74

// ---------------- device scratch (static, no allocation) ----------------
__device__ float g_xn[(size_t)NN * HID];
__device__ float g_xc[(size_t)NC * HID];
__device__ float g_xl[(size_t)NN * HID];
__device__ float g_xr[(size_t)NN * HID];
__device__ int g_deg_m[NC];
__device__ int g_cur_m[NC];
__device__ int g_deg_c[NN];
__device__ int g_cur_c[NN];
__device__ int g_off_m[NC + 1];
__device__ int g_off_c[NN + 1];
__device__ int g_src_m[EE];
__device__ int g_src_c[EE];
__device__ int g_part[128];

// ---------------- f32x2 helpers ----------------
__device__ __forceinline__ void ffma2(unsigned long long& d, unsigned long long a,
                                      unsigned long long b) {
    asm("fma.rn.f32x2 %0, %1, %2, %0;" : "+l"(d) : "l"(a), "l"(b));
}
__device__ __forceinline__ unsigned long long dup2(float x) {
    unsigned long long r;
    asm("mov.b64 %0, {%1, %1};" : "=l"(r) : "f"(x));
    return r;
}
__device__ __forceinline__ unsigned long long pack2(float lo, float hi) {
    unsigned long long r;
    asm("mov.b64 %0, {%1, %2};" : "=l"(r) : "f"(lo), "f"(hi));
    return r;
}
__device__ __forceinline__ float2 unpk2(unsigned long long v) {
    float2 r;
    asm("mov.b64 {%0, %1}, %2;" : "=f"(r.x), "=f"(r.y) : "l"(v));
    return r;
}

// ---------------- merged input projection ----------------
__global__ void proj_both_kernel(const float* __restrict__ Xn, const float* __restrict__ Wn,
                                 const float* __restrict__ bn, float* __restrict__ Yn,
                                 const float* __restrict__ Xc, const float* __restrict__ Wc,
                                 const float* __restrict__ bc, float* __restrict__ Yc) {
    __shared__ float xs[64];
    int blk = blockIdx.x;
    int n = threadIdx.x;  // 128 threads
    const float* X;
    const float* W;
    const float* b;
    float* Y;
    int row, K;
    if (blk < NN) {
        X = Xn; W = Wn; b = bn; Y = Yn; row = blk; K = ND;
    } else {
        X = Xc; W = Wc; b = bc; Y = Yc; row = blk - NN; K = CD;
    }
    if (n < K) xs[n] = X[(size_t)row * K + n];
    __syncthreads();
    float acc = b[n];
    for (int k = 0; k < K; k++) acc = fmaf(xs[k], W[k * HID + n], acc);
    Y[(size_t)row * HID + n] = acc;
}

// ---------------- CSR build ----------------
__global__ void build_zero_kernel(int* __restrict__ dm, int* __restrict__ dc) {
    int i = blockIdx.x * blockDim.x + threadIdx.x;
    if (i < NC) dm[i] = 0;
    if (i < NN) dc[i] = 0;
}
__global__ void build_hist_kernel(const int* __restrict__ mdst, const int* __restrict__ cdst,
                                  int* __restrict__ dm, int* __restrict__ dc, int E) {
    int i = blockIdx.x * blockDim.x + threadIdx.x;
    if (i < E)
        atomicAdd(&dm[mdst[i]], 1);
    else if (i < 2 * E)
        atomicAdd(&dc[cdst[i - E]], 1);
}
__global__ void scanA_kernel(const int* __restrict__ dm, const int* __restrict__ dc,
                             int* __restrict__ part) {
    int b = blockIdx.x;
    const int* deg;
    int n, c0;
    if (b < NB_M) { deg = dm; n = NC; c0 = b * SCHUNK; }
    else          { deg = dc; n = NN; c0 = (b - NB_M) * SCHUNK; }
    int t = threadIdx.x;
    int base = c0 + t * 8;
    int s = 0;
#pragma unroll
    for (int i = 0; i < 8; i++) {
        int idx = base + i;
        if (idx < n) s += deg[idx];
    }
#pragma unroll
    for (int o = 16; o > 0; o >>= 1) s += __shfl_xor_sync(0xffffffffu, s, o);
    __shared__ int red[8];
    if ((t & 31) == 0) red[t >> 5] = s;
    __syncthreads();
    if (t == 0) {
        int tot = 0;
#pragma unroll
        for (int i = 0; i < 8; i++) tot += red[i];
        part[b] = tot;
    }
}
__global__ void scanB_kernel(int* __restrict__ part, int* __restrict__ om,
                             int* __restrict__ oc, int E) {
    __shared__ int sm_[128];
    int t = threadIdx.x;  // 128
    sm_[t] = (t < NB_T) ? part[t] : 0;
    __syncthreads();
    if (t == 0) {
        int run = 0;
        for (int i = 0; i < NB_M; i++) { int x = sm_[i]; sm_[i] = run; run += x; }
        run = 0;
        for (int i = NB_M; i < NB_T; i++) { int x = sm_[i]; sm_[i] = run; run += x; }
        om[NC] = E;
        oc[NN] = E;
    }
    __syncthreads();
    if (t < NB_T) part[t] = sm_[t];
}
__global__ void scanC_kernel(const int* __restrict__ dm, const int* __restrict__ dc,
                             const int* __restrict__ part, int* __restrict__ om,
                             int* __restrict__ oc, int* __restrict__ cm,
                             int* __restrict__ cc) {
    int b = blockIdx.x;
    const int* deg;
    int *off, *cur;
    int n, c0;
    if (b < NB_M) { deg = dm; off = om; cur = cm; n = NC; c0 = b * SCHUNK; }
    else          { deg = dc; off = oc; cur = cc; n = NN; c0 = (b - NB_M) * SCHUNK; }
    int t = threadIdx.x;  // 256
    int base = c0 + t * 8;
    int v[8];
    int s = 0;
#pragma unroll
    for (int i = 0; i < 8; i++) {
        int idx = base + i;
        v[i] = (idx < n) ? deg[idx] : 0;
        s += v[i];
    }
    int lane = t & 31, w = t >> 5;
    int pre = s;
#pragma unroll
    for (int o = 1; o < 32; o <<= 1) {
        int u = __shfl_up_sync(0xffffffffu, pre, o);
        if (lane >= o) pre += u;
    }
    __shared__ int wsum[8];
    if (lane == 31) wsum[w] = pre;
    __syncthreads();
    if (t == 0) {
        int run = 0;
#pragma unroll
        for (int i = 0; i < 8; i++) { int x = wsum[i]; wsum[i] = run; run += x; }
    }
    __syncthreads();
    int ex = pre - s + wsum[w] + part[b];
#pragma unroll
    for (int i = 0; i < 8; i++) {
        int idx = base + i;
        if (idx < n) {
            off[idx] = ex;
            cur[idx] = ex;
            ex += v[i];
        }
    }
}
__global__ void build_scatter_kernel(const int* __restrict__ msrc, const int* __restrict__ mdst,
                                     const int* __restrict__ csrc_e, const int* __restrict__ cdst,
                                     int* __restrict__ cm, int* __restrict__ cc,
                                     int* __restrict__ sm, int* __restrict__ sc, int E) {
    int i = blockIdx.x * blockDim.x + threadIdx.x;
    if (i < E) {
        int p = atomicAdd(&cm[mdst[i]], 1);
        sm[p] = msrc[i];
    } else if (i < 2 * E) {
        int j = i - E;
        int p = atomicAdd(&cc[cdst[j]], 1);
        sc[p] = csrc_e[j];
    }
}

// ---------------- dual SGEMM (f32x2, conflict-free, A pre-duplicated) ----------------
// 256 threads, tile 128x128, BK=8, double-buffered. Thread (tx=tid&15, ty=tid>>4)
// computes rows ty*8..+7, column pairs {32j+2tx, 32j+2tx+1}, j=0..3.
__global__ __launch_bounds__(256, 2)
void sgemm128_dual(const float* __restrict__ X1, const float* __restrict__ W1,
                   const float* __restrict__ b1, float* __restrict__ Y1, int N1, int g1,
                   const float* __restrict__ X2, const float* __restrict__ W2,
                   const float* __restrict__ b2, float* __restrict__ Y2, int N2) {
    __shared__ __align__(16) unsigned long long Ad[2][8][128];  // dup'd A rows, 16KB
    __shared__ __align__(16) float Bs[2][8][128];               // 8KB
    const float* X;
    const float* W;
    const float* bias;
    float* Y;
    int N, rowBase;
    if (blockIdx.x < (unsigned)g1) {
        X = X1; W = W1; bias = b1; Y = Y1; N = N1; rowBase = blockIdx.x * 128;
    } else {
        X = X2; W = W2; bias = b2; Y = Y2; N = N2; rowBase = (blockIdx.x - g1) * 128;
    }
    int tid = threadIdx.x;
    int lr = tid >> 1;            // 0..127 tile row (A load)
    int lk = (tid & 1) * 4;       // 0/4 k offset (A load)
    int wk = tid >> 5;            // 0..7 (B load)
    int wn = (tid & 31) * 4;      // 0..124 (B load)
    int tx = tid & 15;
    int ty = tid >> 4;
    int arow = rowBase + lr;
    bool aok = arow < N;
    const float4 z4 = make_float4(0.f, 0.f, 0.f, 0.f);

    // accumulators initialized to bias pairs
    unsigned long long acc[8][4];
#pragma unroll
    for (int j = 0; j < 4; j++) {
        int c = 32 * j + 2 * tx;
        unsigned long long bp = pack2(bias[c], bias[c + 1]);
#pragma unroll
        for (int i = 0; i < 8; i++) acc[i][j] = bp;
    }

    float4 xv = aok ? *(const float4*)(X + (size_t)arow * HID + lk) : z4;
    float4 wv = *(const float4*)(W + (size_t)wk * HID + wn);
    Ad[0][lk + 0][lr] = dup2(xv.x);
    Ad[0][lk + 1][lr] = dup2(xv.y);
    Ad[0][lk + 2][lr] = dup2(xv.z);
    Ad[0][lk + 3][lr] = dup2(xv.w);
    *(float4*)&Bs[0][wk][wn] = wv;
    __syncthreads();

    int buf = 0;
#pragma unroll 1
    for (int t = 0; t < 16; t++) {
        if (t < 15) {
            int k0 = (t + 1) * 8;
            xv = aok ? *(const float4*)(X + (size_t)arow * HID + k0 + lk) : z4;
            wv = *(const float4*)(W + (size_t)(k0 + wk) * HID + wn);
        }
#pragma unroll
        for (int k = 0; k < 8; k++) {
            ulonglong2 a01 = *(const ulonglong2*)&Ad[buf][k][ty * 8 + 0];
            ulonglong2 a23 = *(const ulonglong2*)&Ad[buf][k][ty * 8 + 2];
            ulonglong2 a45 = *(const ulonglong2*)&Ad[buf][k][ty * 8 + 4];
            ulonglong2 a67 = *(const ulonglong2*)&Ad[buf][k][ty * 8 + 6];
            unsigned long long bd0 = *(const unsigned long long*)&Bs[buf][k][2 * tx];
            unsigned long long bd1 = *(const unsigned long long*)&Bs[buf][k][32 + 2 * tx];
            unsigned long long bd2 = *(const unsigned long long*)&Bs[buf][k][64 + 2 * tx];
            unsigned long long bd3 = *(const unsigned long long*)&Bs[buf][k][96 + 2 * tx];
            unsigned long long av[8] = {a01.x, a01.y, a23.x, a23.y,
                                        a45.x, a45.y, a67.x, a67.y};
            unsigned long long bd[4] = {bd0, bd1, bd2, bd3};
#pragma unroll
            for (int i = 0; i < 8; i++)
#pragma unroll
                for (int j = 0; j < 4; j++) ffma2(acc[i][j], av[i], bd[j]);
        }
        if (t < 15) {
            int nb = buf ^ 1;
            Ad[nb][lk + 0][lr] = dup2(xv.x);
            Ad[nb][lk + 1][lr] = dup2(xv.y);
            Ad[nb][lk + 2][lr] = dup2(xv.z);
            Ad[nb][lk + 3][lr] = dup2(xv.w);
            *(float4*)&Bs[nb][wk][wn] = wv;
            __syncthreads();
            buf = nb;
        }
    }

    // epilogue: bias already folded into acc init
#pragma unroll
    for (int i = 0; i < 8; i++) {
        int row = rowBase + ty * 8 + i;
        if (row < N) {
            float* yp = Y + (size_t)row * HID + 2 * tx;
#pragma unroll
            for (int j = 0; j < 4; j++) {
                float2 p = unpk2(acc[i][j]);
                *(float2*)(yp + 32 * j) = p;
            }
        }
    }
}

// ---------------- fused GATv2: 4-edge-unrolled online softmax + LN ----------------
__device__ __forceinline__ float edge_score(float4 xl4, float4 xr4, float4 at4) {
    float vx = xl4.x + xr4.x; vx = vx > 0.f ? vx : SLOPE * vx;
    float vy = xl4.y + xr4.y; vy = vy > 0.f ? vy : SLOPE * vy;
    float vz = xl4.z + xr4.z; vz = vz > 0.f ? vz : SLOPE * vz;
    float vw = xl4.w + xr4.w; vw = vw > 0.f ? vw : SLOPE * vw;
    float sc = vx * at4.x + vy * at4.y + vz * at4.z + vw * at4.w;
    sc += __shfl_xor_sync(0xffffffffu, sc, 1);
    sc += __shfl_xor_sync(0xffffffffu, sc, 2);
    sc += __shfl_xor_sync(0xffffffffu, sc, 4);
    return sc;
}

__global__ void gat_kernel(const int* __restrict__ off, const int* __restrict__ csrc,
                           const float* __restrict__ xl, const float* __restrict__ xr,
                           const float* __restrict__ att, const float* __restrict__ bias,
                           const float* __restrict__ lng, const float* __restrict__ lnb,
                           float* __restrict__ x, int n_dst) {
    int d = (blockIdx.x * blockDim.x + threadIdx.x) >> 5;
    if (d >= n_dst) return;
    int l = threadIdx.x & 31;
    int ofs = l * 4;

    float4 xr4 = *(const float4*)(xr + (size_t)d * HID + ofs);
    float4 at4 = *(const float4*)(att + ofs);
    int e0 = off[d], e1 = off[d + 1];

    float m = -1e30f, den = 0.f;
    float4 acc = make_float4(0.f, 0.f, 0.f, 0.f);

    for (int e = e0; e < e1; e += 4) {
        int ns = e1 - e;
        int s0 = csrc[e];
        int s1 = (ns > 1) ? csrc[e + 1] : s0;
        int s2 = (ns > 2) ? csrc[e + 2] : s0;
        int s3 = (ns > 3) ? csrc[e + 3] : s0;
        float4 v0 = *(const float4*)(xl + (size_t)s0 * HID + ofs);
        float4 v1 = *(const float4*)(xl + (size_t)s1 * HID + ofs);
        float4 v2 = *(const float4*)(xl + (size_t)s2 * HID + ofs);
        float4 v3 = *(const float4*)(xl + (size_t)s3 * HID + ofs);
        float sc0 = edge_score(v0, xr4, at4);
        float sc1 = edge_score(v1, xr4, at4);
        float sc2 = edge_score(v2, xr4, at4);
        float sc3 = edge_score(v3, xr4, at4);
        if (ns < 4) sc3 = -1e30f;
        if (ns < 3) sc2 = -1e30f;
        if (ns < 2) sc1 = -1e30f;
        float gm = fmaxf(fmaxf(sc0, sc1), fmaxf(sc2, sc3));
        float nm = fmaxf(m, gm);
        float f = __expf(m - nm);
        float e0x = __expf(sc0 - nm);
        float e1x = __expf(sc1 - nm);
        float e2x = __expf(sc2 - nm);
        float e3x = __expf(sc3 - nm);
        den = den * f + ((e0x + e1x) + (e2x + e3x));
        acc.x = acc.x * f + (fmaf(e0x, v0.x, e1x * v1.x) + fmaf(e2x, v2.x, e3x * v3.x));
        acc.y = acc.y * f + (fmaf(e0x, v0.y, e1x * v1.y) + fmaf(e2x, v2.y, e3x * v3.y));
        acc.z = acc.z * f + (fmaf(e0x, v0.z, e1x * v1.z) + fmaf(e2x, v2.z, e3x * v3.z));
        acc.w = acc.w * f + (fmaf(e0x, v0.w, e1x * v1.w) + fmaf(e2x, v2.w, e3x * v3.w));
        m = nm;
    }

    float inv = (e1 > e0) ? 1.0f / den : 0.0f;
    float4 b4 = *(const float4*)(bias + ofs);
    float4 x4 = *(const float4*)(x + (size_t)d * HID + ofs);
    float4 o;
    o.x = acc.x * inv + b4.x + x4.x;
    o.y = acc.y * inv + b4.y + x4.y;
    o.z = acc.z * inv + b4.z + x4.z;
    o.w = acc.w * inv + b4.w + x4.w;

    float s = o.x + o.y + o.z + o.w;
#pragma unroll
    for (int k = 16; k > 0; k >>= 1) s += __shfl_xor_sync(0xffffffffu, s, k);
    float mu = s * (1.0f / HID);
    float q = (o.x - mu) * (o.x - mu) + (o.y - mu) * (o.y - mu) +
              (o.z - mu) * (o.z - mu) + (o.w - mu) * (o.w - mu);
#pragma unroll
    for (int k = 16; k > 0; k >>= 1) q += __shfl_xor_sync(0xffffffffu, q, k);
    float rs = rsqrtf(q * (1.0f / HID) + LNEPS);
    float4 g4 = *(const float4*)(lng + ofs);
    float4 bb4 = *(const float4*)(lnb + ofs);
    o.x = (o.x - mu) * rs * g4.x + bb4.x;
    o.y = (o.y - mu) * rs * g4.y + bb4.y;
    o.z = (o.z - mu) * rs * g4.z + bb4.z;
    o.w = (o.w - mu) * rs * g4.w + bb4.w;
    *(float4*)(x + (size_t)d * HID + ofs) = o;
}

// ---------------- final column mean ----------------
__global__ void zero_out_kernel(float* __restrict__ out) { out[threadIdx.x] = 0.0f; }

__global__ void colmean_kernel(const float* __restrict__ xc, float* __restrict__ out, int N) {
    int t = threadIdx.x;  // 128
    float s = 0.0f;
    for (int r = blockIdx.x; r < N; r += gridDim.x) s += xc[(size_t)r * HID + t];
    atomicAdd(&out[t], s * (1.0f / N));
}

// ---------------- host orchestration ----------------
static inline int ceil_div(int a, int b) { return (a + b - 1) / b; }

extern "C" void kernel_launch(void* const* d_in, const int* in_sizes, int n_in,
                              void* d_out, int out_size) {
    const float* x_node       = (const float*)d_in[0];
    const float* x_class      = (const float*)d_in[1];
    const int*   member_src   = (const int*)d_in[2];
    const int*   member_dst   = (const int*)d_in[3];
    const int*   contains_src = (const int*)d_in[4];
    const int*   contains_dst = (const int*)d_in[5];
    const float* npw = (const float*)d_in[6];
    const float* npb = (const float*)d_in[7];
    const float* cpw = (const float*)d_in[8];
    const float* cpb = (const float*)d_in[9];
    const float* n2c_wl   = (const float*)d_in[10];
    const float* n2c_bl   = (const float*)d_in[11];
    const float* n2c_wr   = (const float*)d_in[12];
    const float* n2c_br   = (const float*)d_in[13];
    const float* n2c_att  = (const float*)d_in[14];
    const float* n2c_bias = (const float*)d_in[15];
    const float* c2n_wl   = (const float*)d_in[16];
    const float* c2n_bl   = (const float*)d_in[17];
    const float* c2n_wr   = (const float*)d_in[18];
    const float* c2n_br   = (const float*)d_in[19];
    const float* c2n_att  = (const float*)d_in[20];
    const float* c2n_bias = (const float*)d_in[21];
    const float* ln_cg = (const float*)d_in[22];
    const float* ln_cb = (const float*)d_in[23];
    const float* ln_ng = (const float*)d_in[24];
    const float* ln_nb = (const float*)d_in[25];
    float* out = (float*)d_out;

    int E = in_sizes[2];

    float *xn, *xc, *xl, *xr;
    int *deg_m, *cur_m, *deg_c, *cur_c, *off_m, *off_c, *src_m, *src_c, *part;
    cudaGetSymbolAddress((void**)&xn, g_xn);
    cudaGetSymbolAddress((void**)&xc, g_xc);
    cudaGetSymbolAddress((void**)&xl, g_xl);
    cudaGetSymbolAddress((void**)&xr, g_xr);
    cudaGetSymbolAddress((void**)&deg_m, g_deg_m);
    cudaGetSymbolAddress((void**)&cur_m, g_cur_m);
    cudaGetSymbolAddress((void**)&deg_c, g_deg_c);
    cudaGetSymbolAddress((void**)&cur_c, g_cur_c);
    cudaGetSymbolAddress((void**)&off_m, g_off_m);
    cudaGetSymbolAddress((void**)&off_c, g_off_c);
    cudaGetSymbolAddress((void**)&src_m, g_src_m);
    cudaGetSymbolAddress((void**)&src_c, g_src_c);
    cudaGetSymbolAddress((void**)&part, g_part);

    int g2E = ceil_div(2 * E, 256);
    int gNNb = ceil_div(NN, 128);
    int gNCb = ceil_div(NC, 128);

    // 0-2: CSR start + projections
    build_zero_kernel<<<ceil_div(NN, 256), 256>>>(deg_m, deg_c);
    build_hist_kernel<<<g2E, 256>>>(member_dst, contains_dst, deg_m, deg_c, E);
    proj_both_kernel<<<NN + NC, 128>>>(x_node, npw, npb, xn, x_class, cpw, cpb, xc);
    // 3: first dual GEMM (ncu profiles launch index 3)
    sgemm128_dual<<<gNNb + gNCb, 256>>>(xn, n2c_wl, n2c_bl, xl, NN, gNNb,
                                        xc, n2c_wr, n2c_br, xr, NC);
    // 4-7: finish CSR
    scanA_kernel<<<NB_T, 256>>>(deg_m, deg_c, part);
    scanB_kernel<<<1, 128>>>(part, off_m, off_c, E);
    scanC_kernel<<<NB_T, 256>>>(deg_m, deg_c, part, off_m, off_c, cur_m, cur_c);
    build_scatter_kernel<<<g2E, 256>>>(member_src, member_dst, contains_src, contains_dst,
                                       cur_m, cur_c, src_m, src_c, E);

    for (int l = 0; l < NL; l++) {
        if (l > 0) {
            sgemm128_dual<<<gNNb + gNCb, 256>>>(xn, n2c_wl + (size_t)l * HID * HID,
                                                n2c_bl + l * HID, xl, NN, gNNb,
                                                xc, n2c_wr + (size_t)l * HID * HID,
                                                n2c_br + l * HID, xr, NC);
        }
        gat_kernel<<<ceil_div(NC * 32, 256), 256>>>(off_m, src_m, xl, xr,
                                                    n2c_att + l * HID, n2c_bias + l * HID,
                                                    ln_cg + l * HID, ln_cb + l * HID,
                                                    xc, NC);
        sgemm128_dual<<<gNCb + gNNb, 256>>>(xc, c2n_wl + (size_t)l * HID * HID,
                                            c2n_bl + l * HID, xl, NC, gNCb,
                                            xn, c2n_wr + (size_t)l * HID * HID,
                                            c2n_br + l * HID, xr, NN);
        gat_kernel<<<ceil_div(NN * 32, 256), 256>>>(off_c, src_c, xl, xr,
                                                    c2n_att + l * HID, c2n_bias + l * HID,
                                                    ln_ng + l * HID, ln_nb + l * HID,
                                                    xn, NN);
    }

    // final: out = mean over rows of xc
    zero_out_kernel<<<1, 128>>>(out);
    colmean_kernel<<<256, 128>>>(xc, out, NC);
}

// round 8
// speedup vs baseline: 1.3569x; 1.3569x over previous
#include <cuda_runtime.h>
#include <cuda_bf16.h>
#include <math.h>
#include <cstdint>

// ---------------- problem constants ----------------
#define NN 100000
#define NC 50000
#define EE 400000
#define ND 43
#define CD 2
#define HID 128
#define NL 4
#define SLOPE 0.2f
#define LNEPS 1e-5f

#define SCHUNK 2048
#define NB_M ((NC + SCHUNK - 1) / SCHUNK)   // 25
#define NB_C ((NN + SCHUNK - 1) / SCHUNK)   // 49
#define NB_T (NB_M + NB_C)                  // 74

// padded K stride for smem tiles (conflict-free fragment loads)
#define PK 136
#define TILE_BYTES (128 * PK * 2)           // 34816 per tile
#define MM_SMEM (4 * TILE_BYTES)            // Xh, Xl, Wh, Wl = 139264

// ---------------- device scratch (static, no allocation) ----------------
__device__ float g_xn[(size_t)NN * HID];
__device__ float g_xc[(size_t)NC * HID];
__device__ float g_xl[(size_t)NN * HID];
__device__ float g_xr[(size_t)NN * HID];
__device__ int g_deg_m[NC];
__device__ int g_cur_m[NC];
__device__ int g_deg_c[NN];
__device__ int g_cur_c[NN];
__device__ int g_off_m[NC + 1];
__device__ int g_off_c[NN + 1];
__device__ int g_src_m[EE];
__device__ int g_src_c[EE];
__device__ int g_part[128];
// transposed+split weights: 16 matrices [n][k] bf16 (idx = group*4 + layer)
__device__ __nv_bfloat16 g_wth[16 * HID * HID];
__device__ __nv_bfloat16 g_wtl[16 * HID * HID];

// ---------------- helpers ----------------
__device__ __forceinline__ void mma16816(float* d, const uint32_t* a, const uint32_t* b) {
    asm volatile(
        "mma.sync.aligned.m16n8k16.row.col.f32.bf16.bf16.f32 "
        "{%0,%1,%2,%3}, {%4,%5,%6,%7}, {%8,%9}, {%0,%1,%2,%3};"
        : "+f"(d[0]), "+f"(d[1]), "+f"(d[2]), "+f"(d[3])
        : "r"(a[0]), "r"(a[1]), "r"(a[2]), "r"(a[3]), "r"(b[0]), "r"(b[1]));
}
__device__ __forceinline__ void split4(float4 x, uint2& hi, uint2& lo) {
    __nv_bfloat162 h01 = __floats2bfloat162_rn(x.x, x.y);
    __nv_bfloat162 h23 = __floats2bfloat162_rn(x.z, x.w);
    float r0 = x.x - __low2float(h01);
    float r1 = x.y - __high2float(h01);
    float r2 = x.z - __low2float(h23);
    float r3 = x.w - __high2float(h23);
    __nv_bfloat162 l01 = __floats2bfloat162_rn(r0, r1);
    __nv_bfloat162 l23 = __floats2bfloat162_rn(r2, r3);
    hi.x = *reinterpret_cast<uint32_t*>(&h01);
    hi.y = *reinterpret_cast<uint32_t*>(&h23);
    lo.x = *reinterpret_cast<uint32_t*>(&l01);
    lo.y = *reinterpret_cast<uint32_t*>(&l23);
}

// ---------------- weight prep: transpose + bf16 split (16 matrices) ----------------
__global__ void prep_weights_kernel(const float* __restrict__ n2c_wl,
                                    const float* __restrict__ n2c_wr,
                                    const float* __restrict__ c2n_wl,
                                    const float* __restrict__ c2n_wr,
                                    __nv_bfloat16* __restrict__ wth,
                                    __nv_bfloat16* __restrict__ wtl) {
    int idx = blockIdx.x;  // 0..15
    int grp = idx >> 2, lay = idx & 3;
    const float* W = (grp == 0) ? n2c_wl : (grp == 1) ? n2c_wr : (grp == 2) ? c2n_wl : c2n_wr;
    W += (size_t)lay * HID * HID;
    __nv_bfloat16* oh = wth + (size_t)idx * HID * HID;
    __nv_bfloat16* ol = wtl + (size_t)idx * HID * HID;
    for (int e = threadIdx.x; e < HID * HID; e += blockDim.x) {
        int k = e >> 7, n = e & 127;
        float w = W[e];  // W[k][n]
        __nv_bfloat16 h = __float2bfloat16_rn(w);
        float r = w - __bfloat162float(h);
        oh[n * HID + k] = h;
        ol[n * HID + k] = __float2bfloat16_rn(r);
    }
}

// ---------------- HMMA dual GEMM: Y[N,128] = X[N,128] @ W + b ------------------------
// bf16 hi/lo split: D = Xh@Wh + Xh@Wl + Xl@Wh, fp32 accum via mma.sync.m16n8k16.
// 256 threads (8 warps), tile 128 rows x 128 cols, K=128 staged once.
// Warp (wm=wid&3, wn=wid>>2): rows wm*32..+31, cols wn*64..+63 (2x8 m16n8 tiles).
__global__ void __launch_bounds__(256, 1)
mm_gemm_dual(const float* __restrict__ X1, const __nv_bfloat16* __restrict__ Wh1,
             const __nv_bfloat16* __restrict__ Wl1, const float* __restrict__ b1,
             float* __restrict__ Y1, int N1, int g1,
             const float* __restrict__ X2, const __nv_bfloat16* __restrict__ Wh2,
             const __nv_bfloat16* __restrict__ Wl2, const float* __restrict__ b2,
             float* __restrict__ Y2, int N2) {
    extern __shared__ char smem[];
    __nv_bfloat16* Xh = (__nv_bfloat16*)(smem);
    __nv_bfloat16* Xl = (__nv_bfloat16*)(smem + TILE_BYTES);
    __nv_bfloat16* Wh = (__nv_bfloat16*)(smem + 2 * TILE_BYTES);
    __nv_bfloat16* Wl = (__nv_bfloat16*)(smem + 3 * TILE_BYTES);

    const float* X;
    const __nv_bfloat16* Gh;
    const __nv_bfloat16* Gl;
    const float* bias;
    float* Y;
    int N, rowBase;
    if (blockIdx.x < (unsigned)g1) {
        X = X1; Gh = Wh1; Gl = Wl1; bias = b1; Y = Y1; N = N1; rowBase = blockIdx.x * 128;
    } else {
        X = X2; Gh = Wh2; Gl = Wl2; bias = b2; Y = Y2; N = N2;
        rowBase = (blockIdx.x - g1) * 128;
    }
    int tid = threadIdx.x;
    int lane = tid & 31;
    int wid = tid >> 5;

    // ---- stage W^T hi/lo (bf16 [n][k] global, uint4 = 8 bf16) ----
#pragma unroll
    for (int it = 0; it < 8; it++) {
        int n = it * 16 + (tid >> 4);
        int kc = (tid & 15) * 8;
        uint4 vh = *reinterpret_cast<const uint4*>(Gh + n * HID + kc);
        uint4 vl = *reinterpret_cast<const uint4*>(Gl + n * HID + kc);
        *reinterpret_cast<uint4*>(&Wh[n * PK + kc]) = vh;
        *reinterpret_cast<uint4*>(&Wl[n * PK + kc]) = vl;
    }
    // ---- stage X hi/lo (fp32 rows -> bf16 split) ----
#pragma unroll
    for (int it = 0; it < 16; it++) {
        int r = it * 8 + (tid >> 5);
        int gr = rowBase + r;
        int kc = (tid & 31) * 4;
        float4 x = (gr < N) ? *reinterpret_cast<const float4*>(X + (size_t)gr * HID + kc)
                            : make_float4(0.f, 0.f, 0.f, 0.f);
        uint2 hi, lo;
        split4(x, hi, lo);
        *reinterpret_cast<uint2*>(&Xh[r * PK + kc]) = hi;
        *reinterpret_cast<uint2*>(&Xl[r * PK + kc]) = lo;
    }
    __syncthreads();

    int row0 = (wid & 3) * 32;
    int col0 = (wid >> 2) * 64;
    int gr4 = lane >> 2;       // 0..7
    int l2 = (lane & 3) * 2;   // 0,2,4,6

    float acc[2][8][4];
#pragma unroll
    for (int mt = 0; mt < 2; mt++)
#pragma unroll
        for (int nt = 0; nt < 8; nt++)
#pragma unroll
            for (int j = 0; j < 4; j++) acc[mt][nt][j] = 0.f;

#pragma unroll 1
    for (int ks = 0; ks < 8; ks++) {
        int k0 = ks * 16;
        uint32_t ah[2][4], al[2][4], bh[8][2], bl[8][2];
#pragma unroll
        for (int mt = 0; mt < 2; mt++) {
            int base = (row0 + mt * 16 + gr4) * PK + k0 + l2;
            ah[mt][0] = *(const uint32_t*)&Xh[base];
            ah[mt][1] = *(const uint32_t*)&Xh[base + 8 * PK];
            ah[mt][2] = *(const uint32_t*)&Xh[base + 8];
            ah[mt][3] = *(const uint32_t*)&Xh[base + 8 * PK + 8];
            al[mt][0] = *(const uint32_t*)&Xl[base];
            al[mt][1] = *(const uint32_t*)&Xl[base + 8 * PK];
            al[mt][2] = *(const uint32_t*)&Xl[base + 8];
            al[mt][3] = *(const uint32_t*)&Xl[base + 8 * PK + 8];
        }
#pragma unroll
        for (int nt = 0; nt < 8; nt++) {
            int base = (col0 + nt * 8 + gr4) * PK + k0 + l2;
            bh[nt][0] = *(const uint32_t*)&Wh[base];
            bh[nt][1] = *(const uint32_t*)&Wh[base + 8];
            bl[nt][0] = *(const uint32_t*)&Wl[base];
            bl[nt][1] = *(const uint32_t*)&Wl[base + 8];
        }
#pragma unroll
        for (int mt = 0; mt < 2; mt++)
#pragma unroll
            for (int nt = 0; nt < 8; nt++) {
                mma16816(acc[mt][nt], ah[mt], bh[nt]);
                mma16816(acc[mt][nt], ah[mt], bl[nt]);
                mma16816(acc[mt][nt], al[mt], bh[nt]);
            }
    }

    // ---- epilogue: +bias, direct stores ----
#pragma unroll
    for (int nt = 0; nt < 8; nt++) {
        int c = col0 + nt * 8 + l2;
        float bx = bias[c], by = bias[c + 1];
#pragma unroll
        for (int mt = 0; mt < 2; mt++) {
            int r0 = rowBase + row0 + mt * 16 + gr4;
            if (r0 < N) {
                float2 v = make_float2(acc[mt][nt][0] + bx, acc[mt][nt][1] + by);
                *reinterpret_cast<float2*>(Y + (size_t)r0 * HID + c) = v;
            }
            if (r0 + 8 < N) {
                float2 v = make_float2(acc[mt][nt][2] + bx, acc[mt][nt][3] + by);
                *reinterpret_cast<float2*>(Y + (size_t)(r0 + 8) * HID + c) = v;
            }
        }
    }
}

// ---------------- merged input projection ----------------
__global__ void proj_both_kernel(const float* __restrict__ Xn, const float* __restrict__ Wn,
                                 const float* __restrict__ bn, float* __restrict__ Yn,
                                 const float* __restrict__ Xc, const float* __restrict__ Wc,
                                 const float* __restrict__ bc, float* __restrict__ Yc) {
    __shared__ float xs[64];
    int blk = blockIdx.x;
    int n = threadIdx.x;  // 128 threads
    const float* X;
    const float* W;
    const float* b;
    float* Y;
    int row, K;
    if (blk < NN) {
        X = Xn; W = Wn; b = bn; Y = Yn; row = blk; K = ND;
    } else {
        X = Xc; W = Wc; b = bc; Y = Yc; row = blk - NN; K = CD;
    }
    if (n < K) xs[n] = X[(size_t)row * K + n];
    __syncthreads();
    float acc = b[n];
    for (int k = 0; k < K; k++) acc = fmaf(xs[k], W[k * HID + n], acc);
    Y[(size_t)row * HID + n] = acc;
}

// ---------------- CSR build ----------------
__global__ void build_zero_kernel(int* __restrict__ dm, int* __restrict__ dc) {
    int i = blockIdx.x * blockDim.x + threadIdx.x;
    if (i < NC) dm[i] = 0;
    if (i < NN) dc[i] = 0;
}
__global__ void build_hist_kernel(const int* __restrict__ mdst, const int* __restrict__ cdst,
                                  int* __restrict__ dm, int* __restrict__ dc, int E) {
    int i = blockIdx.x * blockDim.x + threadIdx.x;
    if (i < E)
        atomicAdd(&dm[mdst[i]], 1);
    else if (i < 2 * E)
        atomicAdd(&dc[cdst[i - E]], 1);
}
__global__ void scanA_kernel(const int* __restrict__ dm, const int* __restrict__ dc,
                             int* __restrict__ part) {
    int b = blockIdx.x;
    const int* deg;
    int n, c0;
    if (b < NB_M) { deg = dm; n = NC; c0 = b * SCHUNK; }
    else          { deg = dc; n = NN; c0 = (b - NB_M) * SCHUNK; }
    int t = threadIdx.x;
    int base = c0 + t * 8;
    int s = 0;
#pragma unroll
    for (int i = 0; i < 8; i++) {
        int idx = base + i;
        if (idx < n) s += deg[idx];
    }
#pragma unroll
    for (int o = 16; o > 0; o >>= 1) s += __shfl_xor_sync(0xffffffffu, s, o);
    __shared__ int red[8];
    if ((t & 31) == 0) red[t >> 5] = s;
    __syncthreads();
    if (t == 0) {
        int tot = 0;
#pragma unroll
        for (int i = 0; i < 8; i++) tot += red[i];
        part[b] = tot;
    }
}
__global__ void scanB_kernel(int* __restrict__ part, int* __restrict__ om,
                             int* __restrict__ oc, int E) {
    __shared__ int sm_[128];
    int t = threadIdx.x;  // 128
    sm_[t] = (t < NB_T) ? part[t] : 0;
    __syncthreads();
    if (t == 0) {
        int run = 0;
        for (int i = 0; i < NB_M; i++) { int x = sm_[i]; sm_[i] = run; run += x; }
        run = 0;
        for (int i = NB_M; i < NB_T; i++) { int x = sm_[i]; sm_[i] = run; run += x; }
        om[NC] = E;
        oc[NN] = E;
    }
    __syncthreads();
    if (t < NB_T) part[t] = sm_[t];
}
__global__ void scanC_kernel(const int* __restrict__ dm, const int* __restrict__ dc,
                             const int* __restrict__ part, int* __restrict__ om,
                             int* __restrict__ oc, int* __restrict__ cm,
                             int* __restrict__ cc) {
    int b = blockIdx.x;
    const int* deg;
    int *off, *cur;
    int n, c0;
    if (b < NB_M) { deg = dm; off = om; cur = cm; n = NC; c0 = b * SCHUNK; }
    else          { deg = dc; off = oc; cur = cc; n = NN; c0 = (b - NB_M) * SCHUNK; }
    int t = threadIdx.x;  // 256
    int base = c0 + t * 8;
    int v[8];
    int s = 0;
#pragma unroll
    for (int i = 0; i < 8; i++) {
        int idx = base + i;
        v[i] = (idx < n) ? deg[idx] : 0;
        s += v[i];
    }
    int lane = t & 31, w = t >> 5;
    int pre = s;
#pragma unroll
    for (int o = 1; o < 32; o <<= 1) {
        int u = __shfl_up_sync(0xffffffffu, pre, o);
        if (lane >= o) pre += u;
    }
    __shared__ int wsum[8];
    if (lane == 31) wsum[w] = pre;
    __syncthreads();
    if (t == 0) {
        int run = 0;
#pragma unroll
        for (int i = 0; i < 8; i++) { int x = wsum[i]; wsum[i] = run; run += x; }
    }
    __syncthreads();
    int ex = pre - s + wsum[w] + part[b];
#pragma unroll
    for (int i = 0; i < 8; i++) {
        int idx = base + i;
        if (idx < n) {
            off[idx] = ex;
            cur[idx] = ex;
            ex += v[i];
        }
    }
}
__global__ void build_scatter_kernel(const int* __restrict__ msrc, const int* __restrict__ mdst,
                                     const int* __restrict__ csrc_e, const int* __restrict__ cdst,
                                     int* __restrict__ cm, int* __restrict__ cc,
                                     int* __restrict__ sm, int* __restrict__ sc, int E) {
    int i = blockIdx.x * blockDim.x + threadIdx.x;
    if (i < E) {
        int p = atomicAdd(&cm[mdst[i]], 1);
        sm[p] = msrc[i];
    } else if (i < 2 * E) {
        int j = i - E;
        int p = atomicAdd(&cc[cdst[j]], 1);
        sc[p] = csrc_e[j];
    }
}

// ---------------- fused GATv2: 4-edge-unrolled online softmax + LN ----------------
__device__ __forceinline__ float edge_score(float4 xl4, float4 xr4, float4 at4) {
    float vx = xl4.x + xr4.x; vx = vx > 0.f ? vx : SLOPE * vx;
    float vy = xl4.y + xr4.y; vy = vy > 0.f ? vy : SLOPE * vy;
    float vz = xl4.z + xr4.z; vz = vz > 0.f ? vz : SLOPE * vz;
    float vw = xl4.w + xr4.w; vw = vw > 0.f ? vw : SLOPE * vw;
    float sc = vx * at4.x + vy * at4.y + vz * at4.z + vw * at4.w;
    sc += __shfl_xor_sync(0xffffffffu, sc, 1);
    sc += __shfl_xor_sync(0xffffffffu, sc, 2);
    sc += __shfl_xor_sync(0xffffffffu, sc, 4);
    return sc;
}

__global__ void gat_kernel(const int* __restrict__ off, const int* __restrict__ csrc,
                           const float* __restrict__ xl, const float* __restrict__ xr,
                           const float* __restrict__ att, const float* __restrict__ bias,
                           const float* __restrict__ lng, const float* __restrict__ lnb,
                           float* __restrict__ x, int n_dst) {
    int d = (blockIdx.x * blockDim.x + threadIdx.x) >> 5;
    if (d >= n_dst) return;
    int l = threadIdx.x & 31;
    int ofs = l * 4;

    float4 xr4 = *(const float4*)(xr + (size_t)d * HID + ofs);
    float4 at4 = *(const float4*)(att + ofs);
    int e0 = off[d], e1 = off[d + 1];

    float m = -1e30f, den = 0.f;
    float4 acc = make_float4(0.f, 0.f, 0.f, 0.f);

    for (int e = e0; e < e1; e += 4) {
        int ns = e1 - e;
        int s0 = csrc[e];
        int s1 = (ns > 1) ? csrc[e + 1] : s0;
        int s2 = (ns > 2) ? csrc[e + 2] : s0;
        int s3 = (ns > 3) ? csrc[e + 3] : s0;
        float4 v0 = *(const float4*)(xl + (size_t)s0 * HID + ofs);
        float4 v1 = *(const float4*)(xl + (size_t)s1 * HID + ofs);
        float4 v2 = *(const float4*)(xl + (size_t)s2 * HID + ofs);
        float4 v3 = *(const float4*)(xl + (size_t)s3 * HID + ofs);
        float sc0 = edge_score(v0, xr4, at4);
        float sc1 = edge_score(v1, xr4, at4);
        float sc2 = edge_score(v2, xr4, at4);
        float sc3 = edge_score(v3, xr4, at4);
        if (ns < 4) sc3 = -1e30f;
        if (ns < 3) sc2 = -1e30f;
        if (ns < 2) sc1 = -1e30f;
        float gm = fmaxf(fmaxf(sc0, sc1), fmaxf(sc2, sc3));
        float nm = fmaxf(m, gm);
        float f = __expf(m - nm);
        float e0x = __expf(sc0 - nm);
        float e1x = __expf(sc1 - nm);
        float e2x = __expf(sc2 - nm);
        float e3x = __expf(sc3 - nm);
        den = den * f + ((e0x + e1x) + (e2x + e3x));
        acc.x = acc.x * f + (fmaf(e0x, v0.x, e1x * v1.x) + fmaf(e2x, v2.x, e3x * v3.x));
        acc.y = acc.y * f + (fmaf(e0x, v0.y, e1x * v1.y) + fmaf(e2x, v2.y, e3x * v3.y));
        acc.z = acc.z * f + (fmaf(e0x, v0.z, e1x * v1.z) + fmaf(e2x, v2.z, e3x * v3.z));
        acc.w = acc.w * f + (fmaf(e0x, v0.w, e1x * v1.w) + fmaf(e2x, v2.w, e3x * v3.w));
        m = nm;
    }

    float inv = (e1 > e0) ? 1.0f / den : 0.0f;
    float4 b4 = *(const float4*)(bias + ofs);
    float4 x4 = *(const float4*)(x + (size_t)d * HID + ofs);
    float4 o;
    o.x = acc.x * inv + b4.x + x4.x;
    o.y = acc.y * inv + b4.y + x4.y;
    o.z = acc.z * inv + b4.z + x4.z;
    o.w = acc.w * inv + b4.w + x4.w;

    float s = o.x + o.y + o.z + o.w;
#pragma unroll
    for (int k = 16; k > 0; k >>= 1) s += __shfl_xor_sync(0xffffffffu, s, k);
    float mu = s * (1.0f / HID);
    float q = (o.x - mu) * (o.x - mu) + (o.y - mu) * (o.y - mu) +
              (o.z - mu) * (o.z - mu) + (o.w - mu) * (o.w - mu);
#pragma unroll
    for (int k = 16; k > 0; k >>= 1) q += __shfl_xor_sync(0xffffffffu, q, k);
    float rs = rsqrtf(q * (1.0f / HID) + LNEPS);
    float4 g4 = *(const float4*)(lng + ofs);
    float4 bb4 = *(const float4*)(lnb + ofs);
    o.x = (o.x - mu) * rs * g4.x + bb4.x;
    o.y = (o.y - mu) * rs * g4.y + bb4.y;
    o.z = (o.z - mu) * rs * g4.z + bb4.z;
    o.w = (o.w - mu) * rs * g4.w + bb4.w;
    *(float4*)(x + (size_t)d * HID + ofs) = o;
}

// ---------------- final column mean ----------------
__global__ void zero_out_kernel(float* __restrict__ out) { out[threadIdx.x] = 0.0f; }

__global__ void colmean_kernel(const float* __restrict__ xc, float* __restrict__ out, int N) {
    int t = threadIdx.x;  // 128
    float s = 0.0f;
    for (int r = blockIdx.x; r < N; r += gridDim.x) s += xc[(size_t)r * HID + t];
    atomicAdd(&out[t], s * (1.0f / N));
}

// ---------------- host orchestration ----------------
static inline int ceil_div(int a, int b) { return (a + b - 1) / b; }

extern "C" void kernel_launch(void* const* d_in, const int* in_sizes, int n_in,
                              void* d_out, int out_size) {
    const float* x_node       = (const float*)d_in[0];
    const float* x_class      = (const float*)d_in[1];
    const int*   member_src   = (const int*)d_in[2];
    const int*   member_dst   = (const int*)d_in[3];
    const int*   contains_src = (const int*)d_in[4];
    const int*   contains_dst = (const int*)d_in[5];
    const float* npw = (const float*)d_in[6];
    const float* npb = (const float*)d_in[7];
    const float* cpw = (const float*)d_in[8];
    const float* cpb = (const float*)d_in[9];
    const float* n2c_wl   = (const float*)d_in[10];
    const float* n2c_bl   = (const float*)d_in[11];
    const float* n2c_wr   = (const float*)d_in[12];
    const float* n2c_br   = (const float*)d_in[13];
    const float* n2c_att  = (const float*)d_in[14];
    const float* n2c_bias = (const float*)d_in[15];
    const float* c2n_wl   = (const float*)d_in[16];
    const float* c2n_bl   = (const float*)d_in[17];
    const float* c2n_wr   = (const float*)d_in[18];
    const float* c2n_br   = (const float*)d_in[19];
    const float* c2n_att  = (const float*)d_in[20];
    const float* c2n_bias = (const float*)d_in[21];
    const float* ln_cg = (const float*)d_in[22];
    const float* ln_cb = (const float*)d_in[23];
    const float* ln_ng = (const float*)d_in[24];
    const float* ln_nb = (const float*)d_in[25];
    float* out = (float*)d_out;

    int E = in_sizes[2];

    float *xn, *xc, *xl, *xr;
    int *deg_m, *cur_m, *deg_c, *cur_c, *off_m, *off_c, *src_m, *src_c, *part;
    __nv_bfloat16 *wth, *wtl;
    cudaGetSymbolAddress((void**)&xn, g_xn);
    cudaGetSymbolAddress((void**)&xc, g_xc);
    cudaGetSymbolAddress((void**)&xl, g_xl);
    cudaGetSymbolAddress((void**)&xr, g_xr);
    cudaGetSymbolAddress((void**)&deg_m, g_deg_m);
    cudaGetSymbolAddress((void**)&cur_m, g_cur_m);
    cudaGetSymbolAddress((void**)&deg_c, g_deg_c);
    cudaGetSymbolAddress((void**)&cur_c, g_cur_c);
    cudaGetSymbolAddress((void**)&off_m, g_off_m);
    cudaGetSymbolAddress((void**)&off_c, g_off_c);
    cudaGetSymbolAddress((void**)&src_m, g_src_m);
    cudaGetSymbolAddress((void**)&src_c, g_src_c);
    cudaGetSymbolAddress((void**)&part, g_part);
    cudaGetSymbolAddress((void**)&wth, g_wth);
    cudaGetSymbolAddress((void**)&wtl, g_wtl);

    cudaFuncSetAttribute(mm_gemm_dual, cudaFuncAttributeMaxDynamicSharedMemorySize, MM_SMEM);

    int g2E = ceil_div(2 * E, 256);
    int gNNb = ceil_div(NN, 128);  // 782
    int gNCb = ceil_div(NC, 128);  // 391

    const size_t WSZ = (size_t)HID * HID;

    // 0: weight transpose+split; 1: input projections
    prep_weights_kernel<<<16, 256>>>(n2c_wl, n2c_wr, c2n_wl, c2n_wr, wth, wtl);
    proj_both_kernel<<<NN + NC, 128>>>(x_node, npw, npb, xn, x_class, cpw, cpb, xc);
    // 2: CSR zero; 3: first GEMM (ncu profiles launch index 3)
    build_zero_kernel<<<ceil_div(NN, 256), 256>>>(deg_m, deg_c);
    mm_gemm_dual<<<gNNb + gNCb, 256, MM_SMEM>>>(
        xn, wth + 0 * 4 * WSZ, wtl + 0 * 4 * WSZ, n2c_bl, xl, NN, gNNb,
        xc, wth + 1 * 4 * WSZ, wtl + 1 * 4 * WSZ, n2c_br, xr, NC);
    // 4-8: finish CSR
    build_hist_kernel<<<g2E, 256>>>(member_dst, contains_dst, deg_m, deg_c, E);
    scanA_kernel<<<NB_T, 256>>>(deg_m, deg_c, part);
    scanB_kernel<<<1, 128>>>(part, off_m, off_c, E);
    scanC_kernel<<<NB_T, 256>>>(deg_m, deg_c, part, off_m, off_c, cur_m, cur_c);
    build_scatter_kernel<<<g2E, 256>>>(member_src, member_dst, contains_src, contains_dst,
                                       cur_m, cur_c, src_m, src_c, E);

    for (int l = 0; l < NL; l++) {
        if (l > 0) {
            mm_gemm_dual<<<gNNb + gNCb, 256, MM_SMEM>>>(
                xn, wth + (0 * 4 + l) * WSZ, wtl + (0 * 4 + l) * WSZ, n2c_bl + l * HID,
                xl, NN, gNNb,
                xc, wth + (1 * 4 + l) * WSZ, wtl + (1 * 4 + l) * WSZ, n2c_br + l * HID,
                xr, NC);
        }
        gat_kernel<<<ceil_div(NC * 32, 256), 256>>>(off_m, src_m, xl, xr,
                                                    n2c_att + l * HID, n2c_bias + l * HID,
                                                    ln_cg + l * HID, ln_cb + l * HID,
                                                    xc, NC);
        mm_gemm_dual<<<gNCb + gNNb, 256, MM_SMEM>>>(
            xc, wth + (2 * 4 + l) * WSZ, wtl + (2 * 4 + l) * WSZ, c2n_bl + l * HID,
            xl, NC, gNCb,
            xn, wth + (3 * 4 + l) * WSZ, wtl + (3 * 4 + l) * WSZ, c2n_br + l * HID,
            xr, NN);
        gat_kernel<<<ceil_div(NN * 32, 256), 256>>>(off_c, src_c, xl, xr,
                                                    c2n_att + l * HID, c2n_bias + l * HID,
                                                    ln_ng + l * HID, ln_nb + l * HID,
                                                    xn, NN);
    }

    // final: out = mean over rows of xc
    zero_out_kernel<<<1, 128>>>(out);
    colmean_kernel<<<256, 128>>>(xc, out, NC);
}

// round 9
// speedup vs baseline: 1.4046x; 1.0352x over previous
#include <cuda_runtime.h>
#include <cuda_bf16.h>
#include <math.h>
#include <cstdint>

// ---------------- problem constants ----------------
#define NN 100000
#define NC 50000
#define EE 400000
#define ND 43
#define CD 2
#define HID 128
#define NL 4
#define SLOPE 0.2f
#define LNEPS 1e-5f

#define SCHUNK 2048
#define NB_M ((NC + SCHUNK - 1) / SCHUNK)   // 25
#define NB_C ((NN + SCHUNK - 1) / SCHUNK)   // 49
#define NB_T (NB_M + NB_C)                  // 74

// padded K stride for smem tiles (conflict-free fragment loads)
#define PK 136
#define W_BYTES (128 * PK * 2)              // 34816 per W tile (hi or lo)
#define X_BYTES (64 * PK * 2)               // 17408 per X half-tile (hi or lo)
#define MM_SMEM (2 * W_BYTES + 2 * X_BYTES) // 104448 -> 2 blocks/SM

// ---------------- device scratch (static, no allocation) ----------------
__device__ float g_xn[(size_t)NN * HID];
__device__ float g_xc[(size_t)NC * HID];
__device__ float g_xl[(size_t)NN * HID];
__device__ float g_xr[(size_t)NN * HID];
__device__ int g_deg_m[NC];
__device__ int g_cur_m[NC];
__device__ int g_deg_c[NN];
__device__ int g_cur_c[NN];
__device__ int g_off_m[NC + 1];
__device__ int g_off_c[NN + 1];
__device__ int g_src_m[EE];
__device__ int g_src_c[EE];
__device__ int g_part[128];
// transposed+split weights: 16 matrices [n][k] bf16 (idx = group*4 + layer)
__device__ __nv_bfloat16 g_wth[16 * HID * HID];
__device__ __nv_bfloat16 g_wtl[16 * HID * HID];

// ---------------- helpers ----------------
__device__ __forceinline__ void mma16816(float* d, const uint32_t* a, const uint32_t* b) {
    asm volatile(
        "mma.sync.aligned.m16n8k16.row.col.f32.bf16.bf16.f32 "
        "{%0,%1,%2,%3}, {%4,%5,%6,%7}, {%8,%9}, {%0,%1,%2,%3};"
        : "+f"(d[0]), "+f"(d[1]), "+f"(d[2]), "+f"(d[3])
        : "r"(a[0]), "r"(a[1]), "r"(a[2]), "r"(a[3]), "r"(b[0]), "r"(b[1]));
}
__device__ __forceinline__ void split4(float4 x, uint2& hi, uint2& lo) {
    __nv_bfloat162 h01 = __floats2bfloat162_rn(x.x, x.y);
    __nv_bfloat162 h23 = __floats2bfloat162_rn(x.z, x.w);
    float r0 = x.x - __low2float(h01);
    float r1 = x.y - __high2float(h01);
    float r2 = x.z - __low2float(h23);
    float r3 = x.w - __high2float(h23);
    __nv_bfloat162 l01 = __floats2bfloat162_rn(r0, r1);
    __nv_bfloat162 l23 = __floats2bfloat162_rn(r2, r3);
    hi.x = *reinterpret_cast<uint32_t*>(&h01);
    hi.y = *reinterpret_cast<uint32_t*>(&h23);
    lo.x = *reinterpret_cast<uint32_t*>(&l01);
    lo.y = *reinterpret_cast<uint32_t*>(&l23);
}

// ---------------- weight prep: transpose + bf16 split (16 matrices) ----------------
__global__ void prep_weights_kernel(const float* __restrict__ n2c_wl,
                                    const float* __restrict__ n2c_wr,
                                    const float* __restrict__ c2n_wl,
                                    const float* __restrict__ c2n_wr,
                                    __nv_bfloat16* __restrict__ wth,
                                    __nv_bfloat16* __restrict__ wtl) {
    int idx = blockIdx.x;  // 0..15
    int grp = idx >> 2, lay = idx & 3;
    const float* W = (grp == 0) ? n2c_wl : (grp == 1) ? n2c_wr : (grp == 2) ? c2n_wl : c2n_wr;
    W += (size_t)lay * HID * HID;
    __nv_bfloat16* oh = wth + (size_t)idx * HID * HID;
    __nv_bfloat16* ol = wtl + (size_t)idx * HID * HID;
    for (int e = threadIdx.x; e < HID * HID; e += blockDim.x) {
        int k = e >> 7, n = e & 127;
        float w = W[e];  // W[k][n]
        __nv_bfloat16 h = __float2bfloat16_rn(w);
        float r = w - __bfloat162float(h);
        oh[n * HID + k] = h;
        ol[n * HID + k] = __float2bfloat16_rn(r);
    }
}

// ---------------- HMMA dual GEMM: Y[N,128] = X[N,128] @ W + b ------------------------
// bf16 hi/lo split: D = Xh@Wh + Xh@Wl + Xl@Wh, fp32 accum via mma.sync.m16n8k16.
// 256 threads (8 warps). Block tile: 128 rows processed as two 64-row halves
// (X half-tile in smem), W (128 cols, hi+lo) staged once. 104KB smem -> 2 blocks/SM.
// Warp (wm=wid&1, wn=wid>>1): rows wm*32..+31 of half, cols wn*32..+31.
__global__ void __launch_bounds__(256, 2)
mm_gemm_dual(const float* __restrict__ X1, const __nv_bfloat16* __restrict__ Wh1,
             const __nv_bfloat16* __restrict__ Wl1, const float* __restrict__ b1,
             float* __restrict__ Y1, int N1, int g1,
             const float* __restrict__ X2, const __nv_bfloat16* __restrict__ Wh2,
             const __nv_bfloat16* __restrict__ Wl2, const float* __restrict__ b2,
             float* __restrict__ Y2, int N2) {
    extern __shared__ char smem[];
    __nv_bfloat16* Wh = (__nv_bfloat16*)(smem);
    __nv_bfloat16* Wl = (__nv_bfloat16*)(smem + W_BYTES);
    __nv_bfloat16* Xh = (__nv_bfloat16*)(smem + 2 * W_BYTES);
    __nv_bfloat16* Xl = (__nv_bfloat16*)(smem + 2 * W_BYTES + X_BYTES);

    const float* X;
    const __nv_bfloat16* Gh;
    const __nv_bfloat16* Gl;
    const float* bias;
    float* Y;
    int N, rowBase;
    if (blockIdx.x < (unsigned)g1) {
        X = X1; Gh = Wh1; Gl = Wl1; bias = b1; Y = Y1; N = N1; rowBase = blockIdx.x * 128;
    } else {
        X = X2; Gh = Wh2; Gl = Wl2; bias = b2; Y = Y2; N = N2;
        rowBase = (blockIdx.x - g1) * 128;
    }
    int tid = threadIdx.x;
    int lane = tid & 31;
    int wid = tid >> 5;

    // ---- stage W^T hi/lo once (bf16 [n][k] global, uint4 = 8 bf16) ----
#pragma unroll
    for (int it = 0; it < 8; it++) {
        int n = it * 16 + (tid >> 4);
        int kc = (tid & 15) * 8;
        uint4 vh = *reinterpret_cast<const uint4*>(Gh + n * HID + kc);
        uint4 vl = *reinterpret_cast<const uint4*>(Gl + n * HID + kc);
        *reinterpret_cast<uint4*>(&Wh[n * PK + kc]) = vh;
        *reinterpret_cast<uint4*>(&Wl[n * PK + kc]) = vl;
    }

    int row0 = (wid & 1) * 32;
    int col0 = (wid >> 1) * 32;
    int gr4 = lane >> 2;       // 0..7
    int l2 = (lane & 3) * 2;   // 0,2,4,6

#pragma unroll 1
    for (int h = 0; h < 2; h++) {
        int rb = rowBase + h * 64;
        // ---- stage X half (fp32 rows -> bf16 hi/lo split) ----
#pragma unroll
        for (int it = 0; it < 8; it++) {
            int r = it * 8 + (tid >> 5);
            int gr = rb + r;
            int kc = (tid & 31) * 4;
            float4 x = (gr < N) ? *reinterpret_cast<const float4*>(X + (size_t)gr * HID + kc)
                                : make_float4(0.f, 0.f, 0.f, 0.f);
            uint2 hi, lo;
            split4(x, hi, lo);
            *reinterpret_cast<uint2*>(&Xh[r * PK + kc]) = hi;
            *reinterpret_cast<uint2*>(&Xl[r * PK + kc]) = lo;
        }
        __syncthreads();

        float acc[2][4][4];
#pragma unroll
        for (int mt = 0; mt < 2; mt++)
#pragma unroll
            for (int nt = 0; nt < 4; nt++)
#pragma unroll
                for (int j = 0; j < 4; j++) acc[mt][nt][j] = 0.f;

#pragma unroll
        for (int ks = 0; ks < 8; ks++) {
            int k0 = ks * 16;
            uint32_t ah[2][4], al[2][4], bh[4][2], bl[4][2];
#pragma unroll
            for (int mt = 0; mt < 2; mt++) {
                int base = (row0 + mt * 16 + gr4) * PK + k0 + l2;
                ah[mt][0] = *(const uint32_t*)&Xh[base];
                ah[mt][1] = *(const uint32_t*)&Xh[base + 8 * PK];
                ah[mt][2] = *(const uint32_t*)&Xh[base + 8];
                ah[mt][3] = *(const uint32_t*)&Xh[base + 8 * PK + 8];
                al[mt][0] = *(const uint32_t*)&Xl[base];
                al[mt][1] = *(const uint32_t*)&Xl[base + 8 * PK];
                al[mt][2] = *(const uint32_t*)&Xl[base + 8];
                al[mt][3] = *(const uint32_t*)&Xl[base + 8 * PK + 8];
            }
#pragma unroll
            for (int nt = 0; nt < 4; nt++) {
                int base = (col0 + nt * 8 + gr4) * PK + k0 + l2;
                bh[nt][0] = *(const uint32_t*)&Wh[base];
                bh[nt][1] = *(const uint32_t*)&Wh[base + 8];
                bl[nt][0] = *(const uint32_t*)&Wl[base];
                bl[nt][1] = *(const uint32_t*)&Wl[base + 8];
            }
#pragma unroll
            for (int mt = 0; mt < 2; mt++)
#pragma unroll
                for (int nt = 0; nt < 4; nt++) {
                    mma16816(acc[mt][nt], ah[mt], bh[nt]);
                    mma16816(acc[mt][nt], ah[mt], bl[nt]);
                    mma16816(acc[mt][nt], al[mt], bh[nt]);
                }
        }

        // ---- epilogue for this half: +bias, direct stores ----
#pragma unroll
        for (int nt = 0; nt < 4; nt++) {
            int c = col0 + nt * 8 + l2;
            float bx = bias[c], by = bias[c + 1];
#pragma unroll
            for (int mt = 0; mt < 2; mt++) {
                int r0 = rb + row0 + mt * 16 + gr4;
                if (r0 < N) {
                    float2 v = make_float2(acc[mt][nt][0] + bx, acc[mt][nt][1] + by);
                    *reinterpret_cast<float2*>(Y + (size_t)r0 * HID + c) = v;
                }
                if (r0 + 8 < N) {
                    float2 v = make_float2(acc[mt][nt][2] + bx, acc[mt][nt][3] + by);
                    *reinterpret_cast<float2*>(Y + (size_t)(r0 + 8) * HID + c) = v;
                }
            }
        }
        __syncthreads();  // X smem reused next half
    }
}

// ---------------- merged input projection ----------------
__global__ void proj_both_kernel(const float* __restrict__ Xn, const float* __restrict__ Wn,
                                 const float* __restrict__ bn, float* __restrict__ Yn,
                                 const float* __restrict__ Xc, const float* __restrict__ Wc,
                                 const float* __restrict__ bc, float* __restrict__ Yc) {
    __shared__ float xs[64];
    int blk = blockIdx.x;
    int n = threadIdx.x;  // 128 threads
    const float* X;
    const float* W;
    const float* b;
    float* Y;
    int row, K;
    if (blk < NN) {
        X = Xn; W = Wn; b = bn; Y = Yn; row = blk; K = ND;
    } else {
        X = Xc; W = Wc; b = bc; Y = Yc; row = blk - NN; K = CD;
    }
    if (n < K) xs[n] = X[(size_t)row * K + n];
    __syncthreads();
    float acc = b[n];
    for (int k = 0; k < K; k++) acc = fmaf(xs[k], W[k * HID + n], acc);
    Y[(size_t)row * HID + n] = acc;
}

// ---------------- CSR build ----------------
__global__ void build_zero_kernel(int* __restrict__ dm, int* __restrict__ dc) {
    int i = blockIdx.x * blockDim.x + threadIdx.x;
    if (i < NC) dm[i] = 0;
    if (i < NN) dc[i] = 0;
}
__global__ void build_hist_kernel(const int* __restrict__ mdst, const int* __restrict__ cdst,
                                  int* __restrict__ dm, int* __restrict__ dc, int E) {
    int i = blockIdx.x * blockDim.x + threadIdx.x;
    if (i < E)
        atomicAdd(&dm[mdst[i]], 1);
    else if (i < 2 * E)
        atomicAdd(&dc[cdst[i - E]], 1);
}
__global__ void scanA_kernel(const int* __restrict__ dm, const int* __restrict__ dc,
                             int* __restrict__ part) {
    int b = blockIdx.x;
    const int* deg;
    int n, c0;
    if (b < NB_M) { deg = dm; n = NC; c0 = b * SCHUNK; }
    else          { deg = dc; n = NN; c0 = (b - NB_M) * SCHUNK; }
    int t = threadIdx.x;
    int base = c0 + t * 8;
    int s = 0;
#pragma unroll
    for (int i = 0; i < 8; i++) {
        int idx = base + i;
        if (idx < n) s += deg[idx];
    }
#pragma unroll
    for (int o = 16; o > 0; o >>= 1) s += __shfl_xor_sync(0xffffffffu, s, o);
    __shared__ int red[8];
    if ((t & 31) == 0) red[t >> 5] = s;
    __syncthreads();
    if (t == 0) {
        int tot = 0;
#pragma unroll
        for (int i = 0; i < 8; i++) tot += red[i];
        part[b] = tot;
    }
}
__global__ void scanB_kernel(int* __restrict__ part, int* __restrict__ om,
                             int* __restrict__ oc, int E) {
    __shared__ int sm_[128];
    int t = threadIdx.x;  // 128
    sm_[t] = (t < NB_T) ? part[t] : 0;
    __syncthreads();
    if (t == 0) {
        int run = 0;
        for (int i = 0; i < NB_M; i++) { int x = sm_[i]; sm_[i] = run; run += x; }
        run = 0;
        for (int i = NB_M; i < NB_T; i++) { int x = sm_[i]; sm_[i] = run; run += x; }
        om[NC] = E;
        oc[NN] = E;
    }
    __syncthreads();
    if (t < NB_T) part[t] = sm_[t];
}
__global__ void scanC_kernel(const int* __restrict__ dm, const int* __restrict__ dc,
                             const int* __restrict__ part, int* __restrict__ om,
                             int* __restrict__ oc, int* __restrict__ cm,
                             int* __restrict__ cc) {
    int b = blockIdx.x;
    const int* deg;
    int *off, *cur;
    int n, c0;
    if (b < NB_M) { deg = dm; off = om; cur = cm; n = NC; c0 = b * SCHUNK; }
    else          { deg = dc; off = oc; cur = cc; n = NN; c0 = (b - NB_M) * SCHUNK; }
    int t = threadIdx.x;  // 256
    int base = c0 + t * 8;
    int v[8];
    int s = 0;
#pragma unroll
    for (int i = 0; i < 8; i++) {
        int idx = base + i;
        v[i] = (idx < n) ? deg[idx] : 0;
        s += v[i];
    }
    int lane = t & 31, w = t >> 5;
    int pre = s;
#pragma unroll
    for (int o = 1; o < 32; o <<= 1) {
        int u = __shfl_up_sync(0xffffffffu, pre, o);
        if (lane >= o) pre += u;
    }
    __shared__ int wsum[8];
    if (lane == 31) wsum[w] = pre;
    __syncthreads();
    if (t == 0) {
        int run = 0;
#pragma unroll
        for (int i = 0; i < 8; i++) { int x = wsum[i]; wsum[i] = run; run += x; }
    }
    __syncthreads();
    int ex = pre - s + wsum[w] + part[b];
#pragma unroll
    for (int i = 0; i < 8; i++) {
        int idx = base + i;
        if (idx < n) {
            off[idx] = ex;
            cur[idx] = ex;
            ex += v[i];
        }
    }
}
__global__ void build_scatter_kernel(const int* __restrict__ msrc, const int* __restrict__ mdst,
                                     const int* __restrict__ csrc_e, const int* __restrict__ cdst,
                                     int* __restrict__ cm, int* __restrict__ cc,
                                     int* __restrict__ sm, int* __restrict__ sc, int E) {
    int i = blockIdx.x * blockDim.x + threadIdx.x;
    if (i < E) {
        int p = atomicAdd(&cm[mdst[i]], 1);
        sm[p] = msrc[i];
    } else if (i < 2 * E) {
        int j = i - E;
        int p = atomicAdd(&cc[cdst[j]], 1);
        sc[p] = csrc_e[j];
    }
}

// ---------------- fused GATv2: 4-edge-unrolled online softmax + LN ----------------
__device__ __forceinline__ float edge_score(float4 xl4, float4 xr4, float4 at4) {
    float vx = xl4.x + xr4.x; vx = vx > 0.f ? vx : SLOPE * vx;
    float vy = xl4.y + xr4.y; vy = vy > 0.f ? vy : SLOPE * vy;
    float vz = xl4.z + xr4.z; vz = vz > 0.f ? vz : SLOPE * vz;
    float vw = xl4.w + xr4.w; vw = vw > 0.f ? vw : SLOPE * vw;
    float sc = vx * at4.x + vy * at4.y + vz * at4.z + vw * at4.w;
    sc += __shfl_xor_sync(0xffffffffu, sc, 1);
    sc += __shfl_xor_sync(0xffffffffu, sc, 2);
    sc += __shfl_xor_sync(0xffffffffu, sc, 4);
    return sc;
}

__global__ void gat_kernel(const int* __restrict__ off, const int* __restrict__ csrc,
                           const float* __restrict__ xl, const float* __restrict__ xr,
                           const float* __restrict__ att, const float* __restrict__ bias,
                           const float* __restrict__ lng, const float* __restrict__ lnb,
                           float* __restrict__ x, int n_dst) {
    int d = (blockIdx.x * blockDim.x + threadIdx.x) >> 5;
    if (d >= n_dst) return;
    int l = threadIdx.x & 31;
    int ofs = l * 4;

    float4 xr4 = *(const float4*)(xr + (size_t)d * HID + ofs);
    float4 at4 = *(const float4*)(att + ofs);
    int e0 = off[d], e1 = off[d + 1];

    float m = -1e30f, den = 0.f;
    float4 acc = make_float4(0.f, 0.f, 0.f, 0.f);

    for (int e = e0; e < e1; e += 4) {
        int ns = e1 - e;
        int s0 = csrc[e];
        int s1 = (ns > 1) ? csrc[e + 1] : s0;
        int s2 = (ns > 2) ? csrc[e + 2] : s0;
        int s3 = (ns > 3) ? csrc[e + 3] : s0;
        float4 v0 = *(const float4*)(xl + (size_t)s0 * HID + ofs);
        float4 v1 = *(const float4*)(xl + (size_t)s1 * HID + ofs);
        float4 v2 = *(const float4*)(xl + (size_t)s2 * HID + ofs);
        float4 v3 = *(const float4*)(xl + (size_t)s3 * HID + ofs);
        float sc0 = edge_score(v0, xr4, at4);
        float sc1 = edge_score(v1, xr4, at4);
        float sc2 = edge_score(v2, xr4, at4);
        float sc3 = edge_score(v3, xr4, at4);
        if (ns < 4) sc3 = -1e30f;
        if (ns < 3) sc2 = -1e30f;
        if (ns < 2) sc1 = -1e30f;
        float gm = fmaxf(fmaxf(sc0, sc1), fmaxf(sc2, sc3));
        float nm = fmaxf(m, gm);
        float f = __expf(m - nm);
        float e0x = __expf(sc0 - nm);
        float e1x = __expf(sc1 - nm);
        float e2x = __expf(sc2 - nm);
        float e3x = __expf(sc3 - nm);
        den = den * f + ((e0x + e1x) + (e2x + e3x));
        acc.x = acc.x * f + (fmaf(e0x, v0.x, e1x * v1.x) + fmaf(e2x, v2.x, e3x * v3.x));
        acc.y = acc.y * f + (fmaf(e0x, v0.y, e1x * v1.y) + fmaf(e2x, v2.y, e3x * v3.y));
        acc.z = acc.z * f + (fmaf(e0x, v0.z, e1x * v1.z) + fmaf(e2x, v2.z, e3x * v3.z));
        acc.w = acc.w * f + (fmaf(e0x, v0.w, e1x * v1.w) + fmaf(e2x, v2.w, e3x * v3.w));
        m = nm;
    }

    float inv = (e1 > e0) ? 1.0f / den : 0.0f;
    float4 b4 = *(const float4*)(bias + ofs);
    float4 x4 = *(const float4*)(x + (size_t)d * HID + ofs);
    float4 o;
    o.x = acc.x * inv + b4.x + x4.x;
    o.y = acc.y * inv + b4.y + x4.y;
    o.z = acc.z * inv + b4.z + x4.z;
    o.w = acc.w * inv + b4.w + x4.w;

    float s = o.x + o.y + o.z + o.w;
#pragma unroll
    for (int k = 16; k > 0; k >>= 1) s += __shfl_xor_sync(0xffffffffu, s, k);
    float mu = s * (1.0f / HID);
    float q = (o.x - mu) * (o.x - mu) + (o.y - mu) * (o.y - mu) +
              (o.z - mu) * (o.z - mu) + (o.w - mu) * (o.w - mu);
#pragma unroll
    for (int k = 16; k > 0; k >>= 1) q += __shfl_xor_sync(0xffffffffu, q, k);
    float rs = rsqrtf(q * (1.0f / HID) + LNEPS);
    float4 g4 = *(const float4*)(lng + ofs);
    float4 bb4 = *(const float4*)(lnb + ofs);
    o.x = (o.x - mu) * rs * g4.x + bb4.x;
    o.y = (o.y - mu) * rs * g4.y + bb4.y;
    o.z = (o.z - mu) * rs * g4.z + bb4.z;
    o.w = (o.w - mu) * rs * g4.w + bb4.w;
    *(float4*)(x + (size_t)d * HID + ofs) = o;
}

// ---------------- final column mean ----------------
__global__ void zero_out_kernel(float* __restrict__ out) { out[threadIdx.x] = 0.0f; }

__global__ void colmean_kernel(const float* __restrict__ xc, float* __restrict__ out, int N) {
    int t = threadIdx.x;  // 128
    float s = 0.0f;
    for (int r = blockIdx.x; r < N; r += gridDim.x) s += xc[(size_t)r * HID + t];
    atomicAdd(&out[t], s * (1.0f / N));
}

// ---------------- host orchestration ----------------
static inline int ceil_div(int a, int b) { return (a + b - 1) / b; }

extern "C" void kernel_launch(void* const* d_in, const int* in_sizes, int n_in,
                              void* d_out, int out_size) {
    const float* x_node       = (const float*)d_in[0];
    const float* x_class      = (const float*)d_in[1];
    const int*   member_src   = (const int*)d_in[2];
    const int*   member_dst   = (const int*)d_in[3];
    const int*   contains_src = (const int*)d_in[4];
    const int*   contains_dst = (const int*)d_in[5];
    const float* npw = (const float*)d_in[6];
    const float* npb = (const float*)d_in[7];
    const float* cpw = (const float*)d_in[8];
    const float* cpb = (const float*)d_in[9];
    const float* n2c_wl   = (const float*)d_in[10];
    const float* n2c_bl   = (const float*)d_in[11];
    const float* n2c_wr   = (const float*)d_in[12];
    const float* n2c_br   = (const float*)d_in[13];
    const float* n2c_att  = (const float*)d_in[14];
    const float* n2c_bias = (const float*)d_in[15];
    const float* c2n_wl   = (const float*)d_in[16];
    const float* c2n_bl   = (const float*)d_in[17];
    const float* c2n_wr   = (const float*)d_in[18];
    const float* c2n_br   = (const float*)d_in[19];
    const float* c2n_att  = (const float*)d_in[20];
    const float* c2n_bias = (const float*)d_in[21];
    const float* ln_cg = (const float*)d_in[22];
    const float* ln_cb = (const float*)d_in[23];
    const float* ln_ng = (const float*)d_in[24];
    const float* ln_nb = (const float*)d_in[25];
    float* out = (float*)d_out;

    int E = in_sizes[2];

    float *xn, *xc, *xl, *xr;
    int *deg_m, *cur_m, *deg_c, *cur_c, *off_m, *off_c, *src_m, *src_c, *part;
    __nv_bfloat16 *wth, *wtl;
    cudaGetSymbolAddress((void**)&xn, g_xn);
    cudaGetSymbolAddress((void**)&xc, g_xc);
    cudaGetSymbolAddress((void**)&xl, g_xl);
    cudaGetSymbolAddress((void**)&xr, g_xr);
    cudaGetSymbolAddress((void**)&deg_m, g_deg_m);
    cudaGetSymbolAddress((void**)&cur_m, g_cur_m);
    cudaGetSymbolAddress((void**)&deg_c, g_deg_c);
    cudaGetSymbolAddress((void**)&cur_c, g_cur_c);
    cudaGetSymbolAddress((void**)&off_m, g_off_m);
    cudaGetSymbolAddress((void**)&off_c, g_off_c);
    cudaGetSymbolAddress((void**)&src_m, g_src_m);
    cudaGetSymbolAddress((void**)&src_c, g_src_c);
    cudaGetSymbolAddress((void**)&part, g_part);
    cudaGetSymbolAddress((void**)&wth, g_wth);
    cudaGetSymbolAddress((void**)&wtl, g_wtl);

    cudaFuncSetAttribute(mm_gemm_dual, cudaFuncAttributeMaxDynamicSharedMemorySize, MM_SMEM);

    int g2E = ceil_div(2 * E, 256);
    int gNNb = ceil_div(NN, 128);  // 782
    int gNCb = ceil_div(NC, 128);  // 391

    const size_t WSZ = (size_t)HID * HID;

    // 0: weight transpose+split; 1: input projections
    prep_weights_kernel<<<16, 256>>>(n2c_wl, n2c_wr, c2n_wl, c2n_wr, wth, wtl);
    proj_both_kernel<<<NN + NC, 128>>>(x_node, npw, npb, xn, x_class, cpw, cpb, xc);
    // 2: CSR zero; 3: first GEMM (ncu profiles launch index 3)
    build_zero_kernel<<<ceil_div(NN, 256), 256>>>(deg_m, deg_c);
    mm_gemm_dual<<<gNNb + gNCb, 256, MM_SMEM>>>(
        xn, wth + 0 * 4 * WSZ, wtl + 0 * 4 * WSZ, n2c_bl, xl, NN, gNNb,
        xc, wth + 1 * 4 * WSZ, wtl + 1 * 4 * WSZ, n2c_br, xr, NC);
    // 4-8: finish CSR
    build_hist_kernel<<<g2E, 256>>>(member_dst, contains_dst, deg_m, deg_c, E);
    scanA_kernel<<<NB_T, 256>>>(deg_m, deg_c, part);
    scanB_kernel<<<1, 128>>>(part, off_m, off_c, E);
    scanC_kernel<<<NB_T, 256>>>(deg_m, deg_c, part, off_m, off_c, cur_m, cur_c);
    build_scatter_kernel<<<g2E, 256>>>(member_src, member_dst, contains_src, contains_dst,
                                       cur_m, cur_c, src_m, src_c, E);

    for (int l = 0; l < NL; l++) {
        if (l > 0) {
            mm_gemm_dual<<<gNNb + gNCb, 256, MM_SMEM>>>(
                xn, wth + (0 * 4 + l) * WSZ, wtl + (0 * 4 + l) * WSZ, n2c_bl + l * HID,
                xl, NN, gNNb,
                xc, wth + (1 * 4 + l) * WSZ, wtl + (1 * 4 + l) * WSZ, n2c_br + l * HID,
                xr, NC);
        }
        gat_kernel<<<ceil_div(NC * 32, 256), 256>>>(off_m, src_m, xl, xr,
                                                    n2c_att + l * HID, n2c_bias + l * HID,
                                                    ln_cg + l * HID, ln_cb + l * HID,
                                                    xc, NC);
        mm_gemm_dual<<<gNCb + gNNb, 256, MM_SMEM>>>(
            xc, wth + (2 * 4 + l) * WSZ, wtl + (2 * 4 + l) * WSZ, c2n_bl + l * HID,
            xl, NC, gNCb,
            xn, wth + (3 * 4 + l) * WSZ, wtl + (3 * 4 + l) * WSZ, c2n_br + l * HID,
            xr, NN);
        gat_kernel<<<ceil_div(NN * 32, 256), 256>>>(off_c, src_c, xl, xr,
                                                    c2n_att + l * HID, c2n_bias + l * HID,
                                                    ln_ng + l * HID, ln_nb + l * HID,
                                                    xn, NN);
    }

    // final: out = mean over rows of xc
    zero_out_kernel<<<1, 128>>>(out);
    colmean_kernel<<<256, 128>>>(xc, out, NC);
}

// round 10
// speedup vs baseline: 1.4227x; 1.0129x over previous
#include <cuda_runtime.h>
#include <cuda_bf16.h>
#include <math.h>
#include <cstdint>

// ---------------- problem constants ----------------
#define NN 100000
#define NC 50000
#define EE 400000
#define ND 43
#define CD 2
#define HID 128
#define NL 4
#define SLOPE 0.2f
#define LNEPS 1e-5f

#define SCHUNK 2048
#define NB_M ((NC + SCHUNK - 1) / SCHUNK)   // 25
#define NB_C ((NN + SCHUNK - 1) / SCHUNK)   // 49
#define NB_T (NB_M + NB_C)                  // 74

// padded K stride for smem tiles (conflict-free ldmatrix rows)
#define PK 136
#define W_BYTES (128 * PK * 2)              // 34816 per W tile (hi or lo)
#define X_BYTES (64 * PK * 2)               // 17408 per X half-tile (hi or lo)
#define MM_SMEM (2 * W_BYTES + 2 * X_BYTES) // 104448 -> 2 blocks/SM
#define XH_OFF (2 * W_BYTES)
#define XL_OFF (2 * W_BYTES + X_BYTES)
#define WL_OFF (W_BYTES)

// ---------------- device scratch (static, no allocation) ----------------
__device__ float g_xn[(size_t)NN * HID];
__device__ float g_xc[(size_t)NC * HID];
__device__ float g_xl[(size_t)NN * HID];
__device__ float g_xr[(size_t)NN * HID];
__device__ int g_deg_m[NC];
__device__ int g_cur_m[NC];
__device__ int g_deg_c[NN];
__device__ int g_cur_c[NN];
__device__ int g_off_m[NC + 1];
__device__ int g_off_c[NN + 1];
__device__ int g_src_m[EE];
__device__ int g_src_c[EE];
__device__ int g_part[128];
// transposed+split weights: 16 matrices [n][k] bf16 (idx = group*4 + layer)
__device__ __nv_bfloat16 g_wth[16 * HID * HID];
__device__ __nv_bfloat16 g_wtl[16 * HID * HID];

// ---------------- helpers ----------------
__device__ __forceinline__ void mma16816(float* d, const uint32_t* a, const uint32_t* b) {
    asm volatile(
        "mma.sync.aligned.m16n8k16.row.col.f32.bf16.bf16.f32 "
        "{%0,%1,%2,%3}, {%4,%5,%6,%7}, {%8,%9}, {%0,%1,%2,%3};"
        : "+f"(d[0]), "+f"(d[1]), "+f"(d[2]), "+f"(d[3])
        : "r"(a[0]), "r"(a[1]), "r"(a[2]), "r"(a[3]), "r"(b[0]), "r"(b[1]));
}
__device__ __forceinline__ void ldsm_x4(uint32_t* r, uint32_t addr) {
    asm volatile("ldmatrix.sync.aligned.m8n8.x4.shared.b16 {%0,%1,%2,%3}, [%4];"
                 : "=r"(r[0]), "=r"(r[1]), "=r"(r[2]), "=r"(r[3])
                 : "r"(addr));
}
__device__ __forceinline__ uint32_t smem_u32(const void* p) {
    uint32_t a;
    asm("{ .reg .u64 t; cvta.to.shared.u64 t, %1; cvt.u32.u64 %0, t; }" : "=r"(a) : "l"(p));
    return a;
}
__device__ __forceinline__ void split4(float4 x, uint2& hi, uint2& lo) {
    __nv_bfloat162 h01 = __floats2bfloat162_rn(x.x, x.y);
    __nv_bfloat162 h23 = __floats2bfloat162_rn(x.z, x.w);
    float r0 = x.x - __low2float(h01);
    float r1 = x.y - __high2float(h01);
    float r2 = x.z - __low2float(h23);
    float r3 = x.w - __high2float(h23);
    __nv_bfloat162 l01 = __floats2bfloat162_rn(r0, r1);
    __nv_bfloat162 l23 = __floats2bfloat162_rn(r2, r3);
    hi.x = *reinterpret_cast<uint32_t*>(&h01);
    hi.y = *reinterpret_cast<uint32_t*>(&h23);
    lo.x = *reinterpret_cast<uint32_t*>(&l01);
    lo.y = *reinterpret_cast<uint32_t*>(&l23);
}

// ---------------- weight prep: transpose + bf16 split (16 matrices) ----------------
__global__ void prep_weights_kernel(const float* __restrict__ n2c_wl,
                                    const float* __restrict__ n2c_wr,
                                    const float* __restrict__ c2n_wl,
                                    const float* __restrict__ c2n_wr,
                                    __nv_bfloat16* __restrict__ wth,
                                    __nv_bfloat16* __restrict__ wtl) {
    int idx = blockIdx.x;  // 0..15
    int grp = idx >> 2, lay = idx & 3;
    const float* W = (grp == 0) ? n2c_wl : (grp == 1) ? n2c_wr : (grp == 2) ? c2n_wl : c2n_wr;
    W += (size_t)lay * HID * HID;
    __nv_bfloat16* oh = wth + (size_t)idx * HID * HID;
    __nv_bfloat16* ol = wtl + (size_t)idx * HID * HID;
    for (int e = threadIdx.x; e < HID * HID; e += blockDim.x) {
        int k = e >> 7, n = e & 127;
        float w = W[e];  // W[k][n]
        __nv_bfloat16 h = __float2bfloat16_rn(w);
        float r = w - __bfloat162float(h);
        oh[n * HID + k] = h;
        ol[n * HID + k] = __float2bfloat16_rn(r);
    }
}

// ---------------- HMMA dual GEMM: Y[N,128] = X[N,128] @ W + b ------------------------
// bf16 hi/lo split: D = Xh@Wh + Xh@Wl + Xl@Wh, fp32 accum via mma.sync.m16n8k16.
// Fragments loaded via ldmatrix.x4 (8 LDSM vs 32 LDS per k-step per warp).
__global__ void __launch_bounds__(256, 2)
mm_gemm_dual(const float* __restrict__ X1, const __nv_bfloat16* __restrict__ Wh1,
             const __nv_bfloat16* __restrict__ Wl1, const float* __restrict__ b1,
             float* __restrict__ Y1, int N1, int g1,
             const float* __restrict__ X2, const __nv_bfloat16* __restrict__ Wh2,
             const __nv_bfloat16* __restrict__ Wl2, const float* __restrict__ b2,
             float* __restrict__ Y2, int N2) {
    extern __shared__ char smem[];
    __nv_bfloat16* Wh = (__nv_bfloat16*)(smem);
    __nv_bfloat16* Wl = (__nv_bfloat16*)(smem + WL_OFF);
    __nv_bfloat16* Xh = (__nv_bfloat16*)(smem + XH_OFF);
    __nv_bfloat16* Xl = (__nv_bfloat16*)(smem + XL_OFF);

    const float* X;
    const __nv_bfloat16* Gh;
    const __nv_bfloat16* Gl;
    const float* bias;
    float* Y;
    int N, rowBase;
    if (blockIdx.x < (unsigned)g1) {
        X = X1; Gh = Wh1; Gl = Wl1; bias = b1; Y = Y1; N = N1; rowBase = blockIdx.x * 128;
    } else {
        X = X2; Gh = Wh2; Gl = Wl2; bias = b2; Y = Y2; N = N2;
        rowBase = (blockIdx.x - g1) * 128;
    }
    int tid = threadIdx.x;
    int lane = tid & 31;
    int wid = tid >> 5;
    uint32_t sbase = smem_u32(smem);

    // ---- stage W^T hi/lo once (bf16 [n][k] global, uint4 = 8 bf16) ----
#pragma unroll
    for (int it = 0; it < 8; it++) {
        int n = it * 16 + (tid >> 4);
        int kc = (tid & 15) * 8;
        uint4 vh = *reinterpret_cast<const uint4*>(Gh + n * HID + kc);
        uint4 vl = *reinterpret_cast<const uint4*>(Gl + n * HID + kc);
        *reinterpret_cast<uint4*>(&Wh[n * PK + kc]) = vh;
        *reinterpret_cast<uint4*>(&Wl[n * PK + kc]) = vl;
    }

    int row0 = (wid & 1) * 32;
    int col0 = (wid >> 1) * 32;
    int gr4 = lane >> 2;       // 0..7
    int l2 = (lane & 3) * 2;   // 0,2,4,6

    // per-lane ldmatrix base byte offsets (k0 = 0)
    // A (m16k16): lane -> row = row0 + (lane&15), k = ((lane>>4)&1)*8
    uint32_t aoff = (uint32_t)(((row0 + (lane & 15)) * PK + ((lane >> 4) & 1) * 8) * 2);
    // B (k16n16 -> two n8 frags): lane -> n = col0 + (lane&7) + ((lane>>4)&1)*8,
    //                             k = ((lane>>3)&1)*8
    uint32_t boff = (uint32_t)(((col0 + (lane & 7) + ((lane >> 4) & 1) * 8) * PK +
                                ((lane >> 3) & 1) * 8) * 2);

#pragma unroll 1
    for (int h = 0; h < 2; h++) {
        int rb = rowBase + h * 64;
        // ---- stage X half (fp32 rows -> bf16 hi/lo split) ----
#pragma unroll
        for (int it = 0; it < 8; it++) {
            int r = it * 8 + (tid >> 5);
            int gr = rb + r;
            int kc = (tid & 31) * 4;
            float4 x = (gr < N) ? *reinterpret_cast<const float4*>(X + (size_t)gr * HID + kc)
                                : make_float4(0.f, 0.f, 0.f, 0.f);
            uint2 hi, lo;
            split4(x, hi, lo);
            *reinterpret_cast<uint2*>(&Xh[r * PK + kc]) = hi;
            *reinterpret_cast<uint2*>(&Xl[r * PK + kc]) = lo;
        }
        __syncthreads();

        float acc[2][4][4];
#pragma unroll
        for (int mt = 0; mt < 2; mt++)
#pragma unroll
            for (int nt = 0; nt < 4; nt++)
#pragma unroll
                for (int j = 0; j < 4; j++) acc[mt][nt][j] = 0.f;

#pragma unroll
        for (int ks = 0; ks < 8; ks++) {
            uint32_t kb = ks * 32;  // 16 bf16 = 32 bytes per k-step
            uint32_t ah[2][4], al[2][4], bh[4][2], bl[4][2];
            uint32_t aXh = sbase + XH_OFF + aoff + kb;
            uint32_t aXl = sbase + XL_OFF + aoff + kb;
            ldsm_x4(ah[0], aXh);
            ldsm_x4(ah[1], aXh + 16 * PK * 2);
            ldsm_x4(al[0], aXl);
            ldsm_x4(al[1], aXl + 16 * PK * 2);
            uint32_t bWh = sbase + boff + kb;
            uint32_t bWl = sbase + WL_OFF + boff + kb;
            ldsm_x4(&bh[0][0], bWh);                 // frags nt=0,1
            ldsm_x4(&bh[2][0], bWh + 16 * PK * 2);   // frags nt=2,3
            ldsm_x4(&bl[0][0], bWl);
            ldsm_x4(&bl[2][0], bWl + 16 * PK * 2);
#pragma unroll
            for (int mt = 0; mt < 2; mt++)
#pragma unroll
                for (int nt = 0; nt < 4; nt++) {
                    mma16816(acc[mt][nt], ah[mt], bh[nt]);
                    mma16816(acc[mt][nt], ah[mt], bl[nt]);
                    mma16816(acc[mt][nt], al[mt], bh[nt]);
                }
        }

        // ---- epilogue for this half: +bias, direct stores ----
#pragma unroll
        for (int nt = 0; nt < 4; nt++) {
            int c = col0 + nt * 8 + l2;
            float bx = bias[c], by = bias[c + 1];
#pragma unroll
            for (int mt = 0; mt < 2; mt++) {
                int r0 = rb + row0 + mt * 16 + gr4;
                if (r0 < N) {
                    float2 v = make_float2(acc[mt][nt][0] + bx, acc[mt][nt][1] + by);
                    *reinterpret_cast<float2*>(Y + (size_t)r0 * HID + c) = v;
                }
                if (r0 + 8 < N) {
                    float2 v = make_float2(acc[mt][nt][2] + bx, acc[mt][nt][3] + by);
                    *reinterpret_cast<float2*>(Y + (size_t)(r0 + 8) * HID + c) = v;
                }
            }
        }
        __syncthreads();  // X smem reused next half
    }
}

// ---------------- merged input projection ----------------
__global__ void proj_both_kernel(const float* __restrict__ Xn, const float* __restrict__ Wn,
                                 const float* __restrict__ bn, float* __restrict__ Yn,
                                 const float* __restrict__ Xc, const float* __restrict__ Wc,
                                 const float* __restrict__ bc, float* __restrict__ Yc) {
    __shared__ float xs[64];
    int blk = blockIdx.x;
    int n = threadIdx.x;  // 128 threads
    const float* X;
    const float* W;
    const float* b;
    float* Y;
    int row, K;
    if (blk < NN) {
        X = Xn; W = Wn; b = bn; Y = Yn; row = blk; K = ND;
    } else {
        X = Xc; W = Wc; b = bc; Y = Yc; row = blk - NN; K = CD;
    }
    if (n < K) xs[n] = X[(size_t)row * K + n];
    __syncthreads();
    float acc = b[n];
    for (int k = 0; k < K; k++) acc = fmaf(xs[k], W[k * HID + n], acc);
    Y[(size_t)row * HID + n] = acc;
}

// ---------------- CSR build ----------------
__global__ void build_zero_kernel(int* __restrict__ dm, int* __restrict__ dc) {
    int i = blockIdx.x * blockDim.x + threadIdx.x;
    if (i < NC) dm[i] = 0;
    if (i < NN) dc[i] = 0;
}
__global__ void build_hist_kernel(const int* __restrict__ mdst, const int* __restrict__ cdst,
                                  int* __restrict__ dm, int* __restrict__ dc, int E) {
    int i = blockIdx.x * blockDim.x + threadIdx.x;
    if (i < E)
        atomicAdd(&dm[mdst[i]], 1);
    else if (i < 2 * E)
        atomicAdd(&dc[cdst[i - E]], 1);
}
__global__ void scanA_kernel(const int* __restrict__ dm, const int* __restrict__ dc,
                             int* __restrict__ part) {
    int b = blockIdx.x;
    const int* deg;
    int n, c0;
    if (b < NB_M) { deg = dm; n = NC; c0 = b * SCHUNK; }
    else          { deg = dc; n = NN; c0 = (b - NB_M) * SCHUNK; }
    int t = threadIdx.x;
    int base = c0 + t * 8;
    int s = 0;
#pragma unroll
    for (int i = 0; i < 8; i++) {
        int idx = base + i;
        if (idx < n) s += deg[idx];
    }
#pragma unroll
    for (int o = 16; o > 0; o >>= 1) s += __shfl_xor_sync(0xffffffffu, s, o);
    __shared__ int red[8];
    if ((t & 31) == 0) red[t >> 5] = s;
    __syncthreads();
    if (t == 0) {
        int tot = 0;
#pragma unroll
        for (int i = 0; i < 8; i++) tot += red[i];
        part[b] = tot;
    }
}
__global__ void scanB_kernel(int* __restrict__ part, int* __restrict__ om,
                             int* __restrict__ oc, int E) {
    __shared__ int sm_[128];
    int t = threadIdx.x;  // 128
    sm_[t] = (t < NB_T) ? part[t] : 0;
    __syncthreads();
    if (t == 0) {
        int run = 0;
        for (int i = 0; i < NB_M; i++) { int x = sm_[i]; sm_[i] = run; run += x; }
        run = 0;
        for (int i = NB_M; i < NB_T; i++) { int x = sm_[i]; sm_[i] = run; run += x; }
        om[NC] = E;
        oc[NN] = E;
    }
    __syncthreads();
    if (t < NB_T) part[t] = sm_[t];
}
__global__ void scanC_kernel(const int* __restrict__ dm, const int* __restrict__ dc,
                             const int* __restrict__ part, int* __restrict__ om,
                             int* __restrict__ oc, int* __restrict__ cm,
                             int* __restrict__ cc) {
    int b = blockIdx.x;
    const int* deg;
    int *off, *cur;
    int n, c0;
    if (b < NB_M) { deg = dm; off = om; cur = cm; n = NC; c0 = b * SCHUNK; }
    else          { deg = dc; off = oc; cur = cc; n = NN; c0 = (b - NB_M) * SCHUNK; }
    int t = threadIdx.x;  // 256
    int base = c0 + t * 8;
    int v[8];
    int s = 0;
#pragma unroll
    for (int i = 0; i < 8; i++) {
        int idx = base + i;
        v[i] = (idx < n) ? deg[idx] : 0;
        s += v[i];
    }
    int lane = t & 31, w = t >> 5;
    int pre = s;
#pragma unroll
    for (int o = 1; o < 32; o <<= 1) {
        int u = __shfl_up_sync(0xffffffffu, pre, o);
        if (lane >= o) pre += u;
    }
    __shared__ int wsum[8];
    if (lane == 31) wsum[w] = pre;
    __syncthreads();
    if (t == 0) {
        int run = 0;
#pragma unroll
        for (int i = 0; i < 8; i++) { int x = wsum[i]; wsum[i] = run; run += x; }
    }
    __syncthreads();
    int ex = pre - s + wsum[w] + part[b];
#pragma unroll
    for (int i = 0; i < 8; i++) {
        int idx = base + i;
        if (idx < n) {
            off[idx] = ex;
            cur[idx] = ex;
            ex += v[i];
        }
    }
}
__global__ void build_scatter_kernel(const int* __restrict__ msrc, const int* __restrict__ mdst,
                                     const int* __restrict__ csrc_e, const int* __restrict__ cdst,
                                     int* __restrict__ cm, int* __restrict__ cc,
                                     int* __restrict__ sm, int* __restrict__ sc, int E) {
    int i = blockIdx.x * blockDim.x + threadIdx.x;
    if (i < E) {
        int p = atomicAdd(&cm[mdst[i]], 1);
        sm[p] = msrc[i];
    } else if (i < 2 * E) {
        int j = i - E;
        int p = atomicAdd(&cc[cdst[j]], 1);
        sc[p] = csrc_e[j];
    }
}

// ---------------- fused GATv2: 4-edge-unrolled online softmax + LN ----------------
__device__ __forceinline__ float edge_score(float4 xl4, float4 xr4, float4 at4) {
    float vx = xl4.x + xr4.x; vx = vx > 0.f ? vx : SLOPE * vx;
    float vy = xl4.y + xr4.y; vy = vy > 0.f ? vy : SLOPE * vy;
    float vz = xl4.z + xr4.z; vz = vz > 0.f ? vz : SLOPE * vz;
    float vw = xl4.w + xr4.w; vw = vw > 0.f ? vw : SLOPE * vw;
    float sc = vx * at4.x + vy * at4.y + vz * at4.z + vw * at4.w;
    sc += __shfl_xor_sync(0xffffffffu, sc, 1);
    sc += __shfl_xor_sync(0xffffffffu, sc, 2);
    sc += __shfl_xor_sync(0xffffffffu, sc, 4);
    return sc;
}

__global__ void gat_kernel(const int* __restrict__ off, const int* __restrict__ csrc,
                           const float* __restrict__ xl, const float* __restrict__ xr,
                           const float* __restrict__ att, const float* __restrict__ bias,
                           const float* __restrict__ lng, const float* __restrict__ lnb,
                           float* __restrict__ x, int n_dst) {
    int d = (blockIdx.x * blockDim.x + threadIdx.x) >> 5;
    if (d >= n_dst) return;
    int l = threadIdx.x & 31;
    int ofs = l * 4;

    float4 xr4 = *(const float4*)(xr + (size_t)d * HID + ofs);
    float4 at4 = *(const float4*)(att + ofs);
    int e0 = off[d], e1 = off[d + 1];

    float m = -1e30f, den = 0.f;
    float4 acc = make_float4(0.f, 0.f, 0.f, 0.f);

    for (int e = e0; e < e1; e += 4) {
        int ns = e1 - e;
        int s0 = csrc[e];
        int s1 = (ns > 1) ? csrc[e + 1] : s0;
        int s2 = (ns > 2) ? csrc[e + 2] : s0;
        int s3 = (ns > 3) ? csrc[e + 3] : s0;
        float4 v0 = *(const float4*)(xl + (size_t)s0 * HID + ofs);
        float4 v1 = *(const float4*)(xl + (size_t)s1 * HID + ofs);
        float4 v2 = *(const float4*)(xl + (size_t)s2 * HID + ofs);
        float4 v3 = *(const float4*)(xl + (size_t)s3 * HID + ofs);
        float sc0 = edge_score(v0, xr4, at4);
        float sc1 = edge_score(v1, xr4, at4);
        float sc2 = edge_score(v2, xr4, at4);
        float sc3 = edge_score(v3, xr4, at4);
        if (ns < 4) sc3 = -1e30f;
        if (ns < 3) sc2 = -1e30f;
        if (ns < 2) sc1 = -1e30f;
        float gm = fmaxf(fmaxf(sc0, sc1), fmaxf(sc2, sc3));
        float nm = fmaxf(m, gm);
        float f = __expf(m - nm);
        float e0x = __expf(sc0 - nm);
        float e1x = __expf(sc1 - nm);
        float e2x = __expf(sc2 - nm);
        float e3x = __expf(sc3 - nm);
        den = den * f + ((e0x + e1x) + (e2x + e3x));
        acc.x = acc.x * f + (fmaf(e0x, v0.x, e1x * v1.x) + fmaf(e2x, v2.x, e3x * v3.x));
        acc.y = acc.y * f + (fmaf(e0x, v0.y, e1x * v1.y) + fmaf(e2x, v2.y, e3x * v3.y));
        acc.z = acc.z * f + (fmaf(e0x, v0.z, e1x * v1.z) + fmaf(e2x, v2.z, e3x * v3.z));
        acc.w = acc.w * f + (fmaf(e0x, v0.w, e1x * v1.w) + fmaf(e2x, v2.w, e3x * v3.w));
        m = nm;
    }

    float inv = (e1 > e0) ? 1.0f / den : 0.0f;
    float4 b4 = *(const float4*)(bias + ofs);
    float4 x4 = *(const float4*)(x + (size_t)d * HID + ofs);
    float4 o;
    o.x = acc.x * inv + b4.x + x4.x;
    o.y = acc.y * inv + b4.y + x4.y;
    o.z = acc.z * inv + b4.z + x4.z;
    o.w = acc.w * inv + b4.w + x4.w;

    float s = o.x + o.y + o.z + o.w;
#pragma unroll
    for (int k = 16; k > 0; k >>= 1) s += __shfl_xor_sync(0xffffffffu, s, k);
    float mu = s * (1.0f / HID);
    float q = (o.x - mu) * (o.x - mu) + (o.y - mu) * (o.y - mu) +
              (o.z - mu) * (o.z - mu) + (o.w - mu) * (o.w - mu);
#pragma unroll
    for (int k = 16; k > 0; k >>= 1) q += __shfl_xor_sync(0xffffffffu, q, k);
    float rs = rsqrtf(q * (1.0f / HID) + LNEPS);
    float4 g4 = *(const float4*)(lng + ofs);
    float4 bb4 = *(const float4*)(lnb + ofs);
    o.x = (o.x - mu) * rs * g4.x + bb4.x;
    o.y = (o.y - mu) * rs * g4.y + bb4.y;
    o.z = (o.z - mu) * rs * g4.z + bb4.z;
    o.w = (o.w - mu) * rs * g4.w + bb4.w;
    *(float4*)(x + (size_t)d * HID + ofs) = o;
}

// ---------------- final column mean ----------------
__global__ void zero_out_kernel(float* __restrict__ out) { out[threadIdx.x] = 0.0f; }

__global__ void colmean_kernel(const float* __restrict__ xc, float* __restrict__ out, int N) {
    int t = threadIdx.x;  // 128
    float s = 0.0f;
    for (int r = blockIdx.x; r < N; r += gridDim.x) s += xc[(size_t)r * HID + t];
    atomicAdd(&out[t], s * (1.0f / N));
}

// ---------------- host orchestration ----------------
static inline int ceil_div(int a, int b) { return (a + b - 1) / b; }

extern "C" void kernel_launch(void* const* d_in, const int* in_sizes, int n_in,
                              void* d_out, int out_size) {
    const float* x_node       = (const float*)d_in[0];
    const float* x_class      = (const float*)d_in[1];
    const int*   member_src   = (const int*)d_in[2];
    const int*   member_dst   = (const int*)d_in[3];
    const int*   contains_src = (const int*)d_in[4];
    const int*   contains_dst = (const int*)d_in[5];
    const float* npw = (const float*)d_in[6];
    const float* npb = (const float*)d_in[7];
    const float* cpw = (const float*)d_in[8];
    const float* cpb = (const float*)d_in[9];
    const float* n2c_wl   = (const float*)d_in[10];
    const float* n2c_bl   = (const float*)d_in[11];
    const float* n2c_wr   = (const float*)d_in[12];
    const float* n2c_br   = (const float*)d_in[13];
    const float* n2c_att  = (const float*)d_in[14];
    const float* n2c_bias = (const float*)d_in[15];
    const float* c2n_wl   = (const float*)d_in[16];
    const float* c2n_bl   = (const float*)d_in[17];
    const float* c2n_wr   = (const float*)d_in[18];
    const float* c2n_br   = (const float*)d_in[19];
    const float* c2n_att  = (const float*)d_in[20];
    const float* c2n_bias = (const float*)d_in[21];
    const float* ln_cg = (const float*)d_in[22];
    const float* ln_cb = (const float*)d_in[23];
    const float* ln_ng = (const float*)d_in[24];
    const float* ln_nb = (const float*)d_in[25];
    float* out = (float*)d_out;

    int E = in_sizes[2];

    float *xn, *xc, *xl, *xr;
    int *deg_m, *cur_m, *deg_c, *cur_c, *off_m, *off_c, *src_m, *src_c, *part;
    __nv_bfloat16 *wth, *wtl;
    cudaGetSymbolAddress((void**)&xn, g_xn);
    cudaGetSymbolAddress((void**)&xc, g_xc);
    cudaGetSymbolAddress((void**)&xl, g_xl);
    cudaGetSymbolAddress((void**)&xr, g_xr);
    cudaGetSymbolAddress((void**)&deg_m, g_deg_m);
    cudaGetSymbolAddress((void**)&cur_m, g_cur_m);
    cudaGetSymbolAddress((void**)&deg_c, g_deg_c);
    cudaGetSymbolAddress((void**)&cur_c, g_cur_c);
    cudaGetSymbolAddress((void**)&off_m, g_off_m);
    cudaGetSymbolAddress((void**)&off_c, g_off_c);
    cudaGetSymbolAddress((void**)&src_m, g_src_m);
    cudaGetSymbolAddress((void**)&src_c, g_src_c);
    cudaGetSymbolAddress((void**)&part, g_part);
    cudaGetSymbolAddress((void**)&wth, g_wth);
    cudaGetSymbolAddress((void**)&wtl, g_wtl);

    cudaFuncSetAttribute(mm_gemm_dual, cudaFuncAttributeMaxDynamicSharedMemorySize, MM_SMEM);

    int g2E = ceil_div(2 * E, 256);
    int gNNb = ceil_div(NN, 128);  // 782
    int gNCb = ceil_div(NC, 128);  // 391

    const size_t WSZ = (size_t)HID * HID;

    // 0: weight transpose+split; 1: input projections
    prep_weights_kernel<<<16, 256>>>(n2c_wl, n2c_wr, c2n_wl, c2n_wr, wth, wtl);
    proj_both_kernel<<<NN + NC, 128>>>(x_node, npw, npb, xn, x_class, cpw, cpb, xc);
    // 2: CSR zero; 3: first GEMM (ncu profiles launch index 3)
    build_zero_kernel<<<ceil_div(NN, 256), 256>>>(deg_m, deg_c);
    mm_gemm_dual<<<gNNb + gNCb, 256, MM_SMEM>>>(
        xn, wth + 0 * 4 * WSZ, wtl + 0 * 4 * WSZ, n2c_bl, xl, NN, gNNb,
        xc, wth + 1 * 4 * WSZ, wtl + 1 * 4 * WSZ, n2c_br, xr, NC);
    // 4-8: finish CSR
    build_hist_kernel<<<g2E, 256>>>(member_dst, contains_dst, deg_m, deg_c, E);
    scanA_kernel<<<NB_T, 256>>>(deg_m, deg_c, part);
    scanB_kernel<<<1, 128>>>(part, off_m, off_c, E);
    scanC_kernel<<<NB_T, 256>>>(deg_m, deg_c, part, off_m, off_c, cur_m, cur_c);
    build_scatter_kernel<<<g2E, 256>>>(member_src, member_dst, contains_src, contains_dst,
                                       cur_m, cur_c, src_m, src_c, E);

    for (int l = 0; l < NL; l++) {
        if (l > 0) {
            mm_gemm_dual<<<gNNb + gNCb, 256, MM_SMEM>>>(
                xn, wth + (0 * 4 + l) * WSZ, wtl + (0 * 4 + l) * WSZ, n2c_bl + l * HID,
                xl, NN, gNNb,
                xc, wth + (1 * 4 + l) * WSZ, wtl + (1 * 4 + l) * WSZ, n2c_br + l * HID,
                xr, NC);
        }
        gat_kernel<<<ceil_div(NC * 32, 256), 256>>>(off_m, src_m, xl, xr,
                                                    n2c_att + l * HID, n2c_bias + l * HID,
                                                    ln_cg + l * HID, ln_cb + l * HID,
                                                    xc, NC);
        mm_gemm_dual<<<gNCb + gNNb, 256, MM_SMEM>>>(
            xc, wth + (2 * 4 + l) * WSZ, wtl + (2 * 4 + l) * WSZ, c2n_bl + l * HID,
            xl, NC, gNCb,
            xn, wth + (3 * 4 + l) * WSZ, wtl + (3 * 4 + l) * WSZ, c2n_br + l * HID,
            xr, NN);
        gat_kernel<<<ceil_div(NN * 32, 256), 256>>>(off_c, src_c, xl, xr,
                                                    c2n_att + l * HID, c2n_bias + l * HID,
                                                    ln_ng + l * HID, ln_nb + l * HID,
                                                    xn, NN);
    }

    // final: out = mean over rows of xc
    zero_out_kernel<<<1, 128>>>(out);
    colmean_kernel<<<256, 128>>>(xc, out, NC);
}

// round 11
// speedup vs baseline: 1.6547x; 1.1631x over previous
#include <cuda_runtime.h>
#include <cuda_bf16.h>
#include <math.h>
#include <cstdint>

// ---------------- problem constants ----------------
#define NN 100000
#define NC 50000
#define EE 400000
#define ND 43
#define CD 2
#define HID 128
#define NL 4
#define SLOPE 0.2f
#define LNEPS 1e-5f

#define SCHUNK 2048
#define NB_M ((NC + SCHUNK - 1) / SCHUNK)   // 25
#define NB_C ((NN + SCHUNK - 1) / SCHUNK)   // 49
#define NB_T (NB_M + NB_C)                  // 74

// padded K stride for smem tiles (conflict-free ldmatrix rows)
#define PK 136
#define W_BYTES (128 * PK * 2)              // 34816 per W tile (hi or lo)
#define X_BYTES (64 * PK * 2)               // 17408 per X tile (hi or lo)
#define MM_SMEM (2 * W_BYTES + 2 * X_BYTES) // 104448 -> 2 blocks/SM
#define XH_OFF (2 * W_BYTES)
#define XL_OFF (2 * W_BYTES + X_BYTES)
#define WL_OFF (W_BYTES)
#define GRIDP 296                            // 2 blocks/SM x 148 SMs

// ---------------- device scratch (static, no allocation) ----------------
__device__ float g_xn[(size_t)NN * HID];
__device__ float g_xc[(size_t)NC * HID];
__device__ float g_xl[(size_t)NN * HID];    // n2c wl output (NN rows)
__device__ float g_xr[(size_t)NC * HID];    // n2c wr output (NC rows)
__device__ float g_xl2[(size_t)NC * HID];   // c2n wl output (NC rows)
__device__ float g_xr2[(size_t)NN * HID];   // c2n wr output (NN rows)
__device__ int g_deg_m[NC];
__device__ int g_cur_m[NC];
__device__ int g_deg_c[NN];
__device__ int g_cur_c[NN];
__device__ int g_off_m[NC + 1];
__device__ int g_off_c[NN + 1];
__device__ int g_src_m[EE];
__device__ int g_src_c[EE];
__device__ int g_part[128];
// transposed+split weights: 16 matrices [n][k] bf16 (idx = group*4 + layer)
__device__ __nv_bfloat16 g_wth[16 * HID * HID];
__device__ __nv_bfloat16 g_wtl[16 * HID * HID];

// ---------------- helpers ----------------
__device__ __forceinline__ void mma16816(float* d, const uint32_t* a, const uint32_t* b) {
    asm volatile(
        "mma.sync.aligned.m16n8k16.row.col.f32.bf16.bf16.f32 "
        "{%0,%1,%2,%3}, {%4,%5,%6,%7}, {%8,%9}, {%0,%1,%2,%3};"
        : "+f"(d[0]), "+f"(d[1]), "+f"(d[2]), "+f"(d[3])
        : "r"(a[0]), "r"(a[1]), "r"(a[2]), "r"(a[3]), "r"(b[0]), "r"(b[1]));
}
__device__ __forceinline__ void ldsm_x4(uint32_t* r, uint32_t addr) {
    asm volatile("ldmatrix.sync.aligned.m8n8.x4.shared.b16 {%0,%1,%2,%3}, [%4];"
                 : "=r"(r[0]), "=r"(r[1]), "=r"(r[2]), "=r"(r[3])
                 : "r"(addr));
}
__device__ __forceinline__ uint32_t smem_u32(const void* p) {
    uint32_t a;
    asm("{ .reg .u64 t; cvta.to.shared.u64 t, %1; cvt.u32.u64 %0, t; }" : "=r"(a) : "l"(p));
    return a;
}
__device__ __forceinline__ void split4(float4 x, uint2& hi, uint2& lo) {
    __nv_bfloat162 h01 = __floats2bfloat162_rn(x.x, x.y);
    __nv_bfloat162 h23 = __floats2bfloat162_rn(x.z, x.w);
    float r0 = x.x - __low2float(h01);
    float r1 = x.y - __high2float(h01);
    float r2 = x.z - __low2float(h23);
    float r3 = x.w - __high2float(h23);
    __nv_bfloat162 l01 = __floats2bfloat162_rn(r0, r1);
    __nv_bfloat162 l23 = __floats2bfloat162_rn(r2, r3);
    hi.x = *reinterpret_cast<uint32_t*>(&h01);
    hi.y = *reinterpret_cast<uint32_t*>(&h23);
    lo.x = *reinterpret_cast<uint32_t*>(&l01);
    lo.y = *reinterpret_cast<uint32_t*>(&l23);
}

// ---------------- weight prep: transpose + bf16 split (16 matrices) ----------------
__global__ void prep_weights_kernel(const float* __restrict__ n2c_wl,
                                    const float* __restrict__ n2c_wr,
                                    const float* __restrict__ c2n_wl,
                                    const float* __restrict__ c2n_wr,
                                    __nv_bfloat16* __restrict__ wth,
                                    __nv_bfloat16* __restrict__ wtl) {
    int idx = blockIdx.x;  // 0..15
    int grp = idx >> 2, lay = idx & 3;
    const float* W = (grp == 0) ? n2c_wl : (grp == 1) ? n2c_wr : (grp == 2) ? c2n_wl : c2n_wr;
    W += (size_t)lay * HID * HID;
    __nv_bfloat16* oh = wth + (size_t)idx * HID * HID;
    __nv_bfloat16* ol = wtl + (size_t)idx * HID * HID;
    for (int e = threadIdx.x; e < HID * HID; e += blockDim.x) {
        int k = e >> 7, n = e & 127;
        float w = W[e];  // W[k][n]
        __nv_bfloat16 h = __float2bfloat16_rn(w);
        float r = w - __bfloat162float(h);
        oh[n * HID + k] = h;
        ol[n * HID + k] = __float2bfloat16_rn(r);
    }
}

// ---------------- persistent HMMA GEMM: Y[N,128] = X[N,128] @ W + b ------------------
// bf16 hi/lo split: D = Xh@Wh + Xh@Wl + Xl@Wh, fp32 accum via mma.sync.m16n8k16.
// Grid = 296 persistent blocks; W staged once per block; 64-row X tiles looped.
__global__ void __launch_bounds__(256, 2)
mm_gemm_p(const float* __restrict__ X, const __nv_bfloat16* __restrict__ Gh,
          const __nv_bfloat16* __restrict__ Gl, const float* __restrict__ bias,
          float* __restrict__ Y, int N) {
    extern __shared__ char smem[];
    __nv_bfloat16* Wh = (__nv_bfloat16*)(smem);
    __nv_bfloat16* Wl = (__nv_bfloat16*)(smem + WL_OFF);
    __nv_bfloat16* Xh = (__nv_bfloat16*)(smem + XH_OFF);
    __nv_bfloat16* Xl = (__nv_bfloat16*)(smem + XL_OFF);

    int tid = threadIdx.x;
    int lane = tid & 31;
    int wid = tid >> 5;
    uint32_t sbase = smem_u32(smem);

    // ---- stage W^T hi/lo once per block ----
#pragma unroll
    for (int it = 0; it < 8; it++) {
        int n = it * 16 + (tid >> 4);
        int kc = (tid & 15) * 8;
        uint4 vh = *reinterpret_cast<const uint4*>(Gh + n * HID + kc);
        uint4 vl = *reinterpret_cast<const uint4*>(Gl + n * HID + kc);
        *reinterpret_cast<uint4*>(&Wh[n * PK + kc]) = vh;
        *reinterpret_cast<uint4*>(&Wl[n * PK + kc]) = vl;
    }

    int row0 = (wid & 1) * 32;
    int col0 = (wid >> 1) * 32;
    int gr4 = lane >> 2;       // 0..7
    int l2 = (lane & 3) * 2;   // 0,2,4,6

    // per-lane ldmatrix base byte offsets
    uint32_t aoff = (uint32_t)(((row0 + (lane & 15)) * PK + ((lane >> 4) & 1) * 8) * 2);
    uint32_t boff = (uint32_t)(((col0 + (lane & 7) + ((lane >> 4) & 1) * 8) * PK +
                                ((lane >> 3) & 1) * 8) * 2);

    int ntiles = (N + 63) >> 6;
#pragma unroll 1
    for (int t = blockIdx.x; t < ntiles; t += gridDim.x) {
        int rb = t * 64;
        __syncthreads();  // previous tile's smem readers done (also covers W stage)
        // ---- stage X tile (fp32 rows -> bf16 hi/lo split) ----
#pragma unroll
        for (int it = 0; it < 8; it++) {
            int r = it * 8 + (tid >> 5);
            int gr = rb + r;
            int kc = (tid & 31) * 4;
            float4 x = (gr < N) ? *reinterpret_cast<const float4*>(X + (size_t)gr * HID + kc)
                                : make_float4(0.f, 0.f, 0.f, 0.f);
            uint2 hi, lo;
            split4(x, hi, lo);
            *reinterpret_cast<uint2*>(&Xh[r * PK + kc]) = hi;
            *reinterpret_cast<uint2*>(&Xl[r * PK + kc]) = lo;
        }
        __syncthreads();

        float acc[2][4][4];
#pragma unroll
        for (int mt = 0; mt < 2; mt++)
#pragma unroll
            for (int nt = 0; nt < 4; nt++)
#pragma unroll
                for (int j = 0; j < 4; j++) acc[mt][nt][j] = 0.f;

#pragma unroll
        for (int ks = 0; ks < 8; ks++) {
            uint32_t kb = ks * 32;  // 16 bf16 = 32 bytes per k-step
            uint32_t ah[2][4], al[2][4], bh[4][2], bl[4][2];
            uint32_t aXh = sbase + XH_OFF + aoff + kb;
            uint32_t aXl = sbase + XL_OFF + aoff + kb;
            ldsm_x4(ah[0], aXh);
            ldsm_x4(ah[1], aXh + 16 * PK * 2);
            ldsm_x4(al[0], aXl);
            ldsm_x4(al[1], aXl + 16 * PK * 2);
            uint32_t bWh = sbase + boff + kb;
            uint32_t bWl = sbase + WL_OFF + boff + kb;
            ldsm_x4(&bh[0][0], bWh);
            ldsm_x4(&bh[2][0], bWh + 16 * PK * 2);
            ldsm_x4(&bl[0][0], bWl);
            ldsm_x4(&bl[2][0], bWl + 16 * PK * 2);
#pragma unroll
            for (int mt = 0; mt < 2; mt++)
#pragma unroll
                for (int nt = 0; nt < 4; nt++) {
                    mma16816(acc[mt][nt], ah[mt], bh[nt]);
                    mma16816(acc[mt][nt], ah[mt], bl[nt]);
                    mma16816(acc[mt][nt], al[mt], bh[nt]);
                }
        }

        // ---- epilogue: +bias, direct stores ----
#pragma unroll
        for (int nt = 0; nt < 4; nt++) {
            int c = col0 + nt * 8 + l2;
            float bx = bias[c], by = bias[c + 1];
#pragma unroll
            for (int mt = 0; mt < 2; mt++) {
                int r0 = rb + row0 + mt * 16 + gr4;
                if (r0 < N) {
                    float2 v = make_float2(acc[mt][nt][0] + bx, acc[mt][nt][1] + by);
                    *reinterpret_cast<float2*>(Y + (size_t)r0 * HID + c) = v;
                }
                if (r0 + 8 < N) {
                    float2 v = make_float2(acc[mt][nt][2] + bx, acc[mt][nt][3] + by);
                    *reinterpret_cast<float2*>(Y + (size_t)(r0 + 8) * HID + c) = v;
                }
            }
        }
    }
}

// ---------------- merged input projection ----------------
__global__ void proj_both_kernel(const float* __restrict__ Xn, const float* __restrict__ Wn,
                                 const float* __restrict__ bn, float* __restrict__ Yn,
                                 const float* __restrict__ Xc, const float* __restrict__ Wc,
                                 const float* __restrict__ bc, float* __restrict__ Yc) {
    __shared__ float xs[64];
    int blk = blockIdx.x;
    int n = threadIdx.x;  // 128 threads
    const float* X;
    const float* W;
    const float* b;
    float* Y;
    int row, K;
    if (blk < NN) {
        X = Xn; W = Wn; b = bn; Y = Yn; row = blk; K = ND;
    } else {
        X = Xc; W = Wc; b = bc; Y = Yc; row = blk - NN; K = CD;
    }
    if (n < K) xs[n] = X[(size_t)row * K + n];
    __syncthreads();
    float acc = b[n];
    for (int k = 0; k < K; k++) acc = fmaf(xs[k], W[k * HID + n], acc);
    Y[(size_t)row * HID + n] = acc;
}

// ---------------- CSR build ----------------
__global__ void build_zero_kernel(int* __restrict__ dm, int* __restrict__ dc) {
    int i = blockIdx.x * blockDim.x + threadIdx.x;
    if (i < NC) dm[i] = 0;
    if (i < NN) dc[i] = 0;
}
__global__ void build_hist_kernel(const int* __restrict__ mdst, const int* __restrict__ cdst,
                                  int* __restrict__ dm, int* __restrict__ dc, int E) {
    int i = blockIdx.x * blockDim.x + threadIdx.x;
    if (i < E)
        atomicAdd(&dm[mdst[i]], 1);
    else if (i < 2 * E)
        atomicAdd(&dc[cdst[i - E]], 1);
}
__global__ void scanA_kernel(const int* __restrict__ dm, const int* __restrict__ dc,
                             int* __restrict__ part) {
    int b = blockIdx.x;
    const int* deg;
    int n, c0;
    if (b < NB_M) { deg = dm; n = NC; c0 = b * SCHUNK; }
    else          { deg = dc; n = NN; c0 = (b - NB_M) * SCHUNK; }
    int t = threadIdx.x;
    int base = c0 + t * 8;
    int s = 0;
#pragma unroll
    for (int i = 0; i < 8; i++) {
        int idx = base + i;
        if (idx < n) s += deg[idx];
    }
#pragma unroll
    for (int o = 16; o > 0; o >>= 1) s += __shfl_xor_sync(0xffffffffu, s, o);
    __shared__ int red[8];
    if ((t & 31) == 0) red[t >> 5] = s;
    __syncthreads();
    if (t == 0) {
        int tot = 0;
#pragma unroll
        for (int i = 0; i < 8; i++) tot += red[i];
        part[b] = tot;
    }
}
__global__ void scanB_kernel(int* __restrict__ part, int* __restrict__ om,
                             int* __restrict__ oc, int E) {
    __shared__ int sm_[128];
    int t = threadIdx.x;  // 128
    sm_[t] = (t < NB_T) ? part[t] : 0;
    __syncthreads();
    if (t == 0) {
        int run = 0;
        for (int i = 0; i < NB_M; i++) { int x = sm_[i]; sm_[i] = run; run += x; }
        run = 0;
        for (int i = NB_M; i < NB_T; i++) { int x = sm_[i]; sm_[i] = run; run += x; }
        om[NC] = E;
        oc[NN] = E;
    }
    __syncthreads();
    if (t < NB_T) part[t] = sm_[t];
}
__global__ void scanC_kernel(const int* __restrict__ dm, const int* __restrict__ dc,
                             const int* __restrict__ part, int* __restrict__ om,
                             int* __restrict__ oc, int* __restrict__ cm,
                             int* __restrict__ cc) {
    int b = blockIdx.x;
    const int* deg;
    int *off, *cur;
    int n, c0;
    if (b < NB_M) { deg = dm; off = om; cur = cm; n = NC; c0 = b * SCHUNK; }
    else          { deg = dc; off = oc; cur = cc; n = NN; c0 = (b - NB_M) * SCHUNK; }
    int t = threadIdx.x;  // 256
    int base = c0 + t * 8;
    int v[8];
    int s = 0;
#pragma unroll
    for (int i = 0; i < 8; i++) {
        int idx = base + i;
        v[i] = (idx < n) ? deg[idx] : 0;
        s += v[i];
    }
    int lane = t & 31, w = t >> 5;
    int pre = s;
#pragma unroll
    for (int o = 1; o < 32; o <<= 1) {
        int u = __shfl_up_sync(0xffffffffu, pre, o);
        if (lane >= o) pre += u;
    }
    __shared__ int wsum[8];
    if (lane == 31) wsum[w] = pre;
    __syncthreads();
    if (t == 0) {
        int run = 0;
#pragma unroll
        for (int i = 0; i < 8; i++) { int x = wsum[i]; wsum[i] = run; run += x; }
    }
    __syncthreads();
    int ex = pre - s + wsum[w] + part[b];
#pragma unroll
    for (int i = 0; i < 8; i++) {
        int idx = base + i;
        if (idx < n) {
            off[idx] = ex;
            cur[idx] = ex;
            ex += v[i];
        }
    }
}
__global__ void build_scatter_kernel(const int* __restrict__ msrc, const int* __restrict__ mdst,
                                     const int* __restrict__ csrc_e, const int* __restrict__ cdst,
                                     int* __restrict__ cm, int* __restrict__ cc,
                                     int* __restrict__ sm, int* __restrict__ sc, int E) {
    int i = blockIdx.x * blockDim.x + threadIdx.x;
    if (i < E) {
        int p = atomicAdd(&cm[mdst[i]], 1);
        sm[p] = msrc[i];
    } else if (i < 2 * E) {
        int j = i - E;
        int p = atomicAdd(&cc[cdst[j]], 1);
        sc[p] = csrc_e[j];
    }
}

// ---------------- fused GATv2: 4-edge-unrolled online softmax + LN ----------------
__device__ __forceinline__ float edge_score(float4 xl4, float4 xr4, float4 at4) {
    float vx = xl4.x + xr4.x; vx = vx > 0.f ? vx : SLOPE * vx;
    float vy = xl4.y + xr4.y; vy = vy > 0.f ? vy : SLOPE * vy;
    float vz = xl4.z + xr4.z; vz = vz > 0.f ? vz : SLOPE * vz;
    float vw = xl4.w + xr4.w; vw = vw > 0.f ? vw : SLOPE * vw;
    float sc = vx * at4.x + vy * at4.y + vz * at4.z + vw * at4.w;
    sc += __shfl_xor_sync(0xffffffffu, sc, 1);
    sc += __shfl_xor_sync(0xffffffffu, sc, 2);
    sc += __shfl_xor_sync(0xffffffffu, sc, 4);
    return sc;
}

__global__ void gat_kernel(const int* __restrict__ off, const int* __restrict__ csrc,
                           const float* __restrict__ xl, const float* __restrict__ xr,
                           const float* __restrict__ att, const float* __restrict__ bias,
                           const float* __restrict__ lng, const float* __restrict__ lnb,
                           float* __restrict__ x, int n_dst) {
    int d = (blockIdx.x * blockDim.x + threadIdx.x) >> 5;
    if (d >= n_dst) return;
    int l = threadIdx.x & 31;
    int ofs = l * 4;

    float4 xr4 = *(const float4*)(xr + (size_t)d * HID + ofs);
    float4 at4 = *(const float4*)(att + ofs);
    int e0 = off[d], e1 = off[d + 1];

    float m = -1e30f, den = 0.f;
    float4 acc = make_float4(0.f, 0.f, 0.f, 0.f);

    for (int e = e0; e < e1; e += 4) {
        int ns = e1 - e;
        int s0 = csrc[e];
        int s1 = (ns > 1) ? csrc[e + 1] : s0;
        int s2 = (ns > 2) ? csrc[e + 2] : s0;
        int s3 = (ns > 3) ? csrc[e + 3] : s0;
        float4 v0 = *(const float4*)(xl + (size_t)s0 * HID + ofs);
        float4 v1 = *(const float4*)(xl + (size_t)s1 * HID + ofs);
        float4 v2 = *(const float4*)(xl + (size_t)s2 * HID + ofs);
        float4 v3 = *(const float4*)(xl + (size_t)s3 * HID + ofs);
        float sc0 = edge_score(v0, xr4, at4);
        float sc1 = edge_score(v1, xr4, at4);
        float sc2 = edge_score(v2, xr4, at4);
        float sc3 = edge_score(v3, xr4, at4);
        if (ns < 4) sc3 = -1e30f;
        if (ns < 3) sc2 = -1e30f;
        if (ns < 2) sc1 = -1e30f;
        float gm = fmaxf(fmaxf(sc0, sc1), fmaxf(sc2, sc3));
        float nm = fmaxf(m, gm);
        float f = __expf(m - nm);
        float e0x = __expf(sc0 - nm);
        float e1x = __expf(sc1 - nm);
        float e2x = __expf(sc2 - nm);
        float e3x = __expf(sc3 - nm);
        den = den * f + ((e0x + e1x) + (e2x + e3x));
        acc.x = acc.x * f + (fmaf(e0x, v0.x, e1x * v1.x) + fmaf(e2x, v2.x, e3x * v3.x));
        acc.y = acc.y * f + (fmaf(e0x, v0.y, e1x * v1.y) + fmaf(e2x, v2.y, e3x * v3.y));
        acc.z = acc.z * f + (fmaf(e0x, v0.z, e1x * v1.z) + fmaf(e2x, v2.z, e3x * v3.z));
        acc.w = acc.w * f + (fmaf(e0x, v0.w, e1x * v1.w) + fmaf(e2x, v2.w, e3x * v3.w));
        m = nm;
    }

    float inv = (e1 > e0) ? 1.0f / den : 0.0f;
    float4 b4 = *(const float4*)(bias + ofs);
    float4 x4 = *(const float4*)(x + (size_t)d * HID + ofs);
    float4 o;
    o.x = acc.x * inv + b4.x + x4.x;
    o.y = acc.y * inv + b4.y + x4.y;
    o.z = acc.z * inv + b4.z + x4.z;
    o.w = acc.w * inv + b4.w + x4.w;

    float s = o.x + o.y + o.z + o.w;
#pragma unroll
    for (int k = 16; k > 0; k >>= 1) s += __shfl_xor_sync(0xffffffffu, s, k);
    float mu = s * (1.0f / HID);
    float q = (o.x - mu) * (o.x - mu) + (o.y - mu) * (o.y - mu) +
              (o.z - mu) * (o.z - mu) + (o.w - mu) * (o.w - mu);
#pragma unroll
    for (int k = 16; k > 0; k >>= 1) q += __shfl_xor_sync(0xffffffffu, q, k);
    float rs = rsqrtf(q * (1.0f / HID) + LNEPS);
    float4 g4 = *(const float4*)(lng + ofs);
    float4 bb4 = *(const float4*)(lnb + ofs);
    o.x = (o.x - mu) * rs * g4.x + bb4.x;
    o.y = (o.y - mu) * rs * g4.y + bb4.y;
    o.z = (o.z - mu) * rs * g4.z + bb4.z;
    o.w = (o.w - mu) * rs * g4.w + bb4.w;
    *(float4*)(x + (size_t)d * HID + ofs) = o;
}

// ---------------- final column mean ----------------
__global__ void zero_out_kernel(float* __restrict__ out) { out[threadIdx.x] = 0.0f; }

__global__ void colmean_kernel(const float* __restrict__ xc, float* __restrict__ out, int N) {
    int t = threadIdx.x;  // 128
    float s = 0.0f;
    for (int r = blockIdx.x; r < N; r += gridDim.x) s += xc[(size_t)r * HID + t];
    atomicAdd(&out[t], s * (1.0f / N));
}

// ---------------- host orchestration ----------------
static inline int ceil_div(int a, int b) { return (a + b - 1) / b; }

extern "C" void kernel_launch(void* const* d_in, const int* in_sizes, int n_in,
                              void* d_out, int out_size) {
    const float* x_node       = (const float*)d_in[0];
    const float* x_class      = (const float*)d_in[1];
    const int*   member_src   = (const int*)d_in[2];
    const int*   member_dst   = (const int*)d_in[3];
    const int*   contains_src = (const int*)d_in[4];
    const int*   contains_dst = (const int*)d_in[5];
    const float* npw = (const float*)d_in[6];
    const float* npb = (const float*)d_in[7];
    const float* cpw = (const float*)d_in[8];
    const float* cpb = (const float*)d_in[9];
    const float* n2c_wl   = (const float*)d_in[10];
    const float* n2c_bl   = (const float*)d_in[11];
    const float* n2c_wr   = (const float*)d_in[12];
    const float* n2c_br   = (const float*)d_in[13];
    const float* n2c_att  = (const float*)d_in[14];
    const float* n2c_bias = (const float*)d_in[15];
    const float* c2n_wl   = (const float*)d_in[16];
    const float* c2n_bl   = (const float*)d_in[17];
    const float* c2n_wr   = (const float*)d_in[18];
    const float* c2n_br   = (const float*)d_in[19];
    const float* c2n_att  = (const float*)d_in[20];
    const float* c2n_bias = (const float*)d_in[21];
    const float* ln_cg = (const float*)d_in[22];
    const float* ln_cb = (const float*)d_in[23];
    const float* ln_ng = (const float*)d_in[24];
    const float* ln_nb = (const float*)d_in[25];
    float* out = (float*)d_out;

    int E = in_sizes[2];

    float *xn, *xc, *xl, *xr, *xl2, *xr2;
    int *deg_m, *cur_m, *deg_c, *cur_c, *off_m, *off_c, *src_m, *src_c, *part;
    __nv_bfloat16 *wth, *wtl;
    cudaGetSymbolAddress((void**)&xn, g_xn);
    cudaGetSymbolAddress((void**)&xc, g_xc);
    cudaGetSymbolAddress((void**)&xl, g_xl);
    cudaGetSymbolAddress((void**)&xr, g_xr);
    cudaGetSymbolAddress((void**)&xl2, g_xl2);
    cudaGetSymbolAddress((void**)&xr2, g_xr2);
    cudaGetSymbolAddress((void**)&deg_m, g_deg_m);
    cudaGetSymbolAddress((void**)&cur_m, g_cur_m);
    cudaGetSymbolAddress((void**)&deg_c, g_deg_c);
    cudaGetSymbolAddress((void**)&cur_c, g_cur_c);
    cudaGetSymbolAddress((void**)&off_m, g_off_m);
    cudaGetSymbolAddress((void**)&off_c, g_off_c);
    cudaGetSymbolAddress((void**)&src_m, g_src_m);
    cudaGetSymbolAddress((void**)&src_c, g_src_c);
    cudaGetSymbolAddress((void**)&part, g_part);
    cudaGetSymbolAddress((void**)&wth, g_wth);
    cudaGetSymbolAddress((void**)&wtl, g_wtl);

    cudaFuncSetAttribute(mm_gemm_p, cudaFuncAttributeMaxDynamicSharedMemorySize, MM_SMEM);

    // persistent side stream + fork/join events (created once; host-side only)
    static cudaStream_t s1 = nullptr;
    static cudaEvent_t ev[6];
    if (s1 == nullptr) {
        cudaStreamCreateWithFlags(&s1, cudaStreamNonBlocking);
        for (int i = 0; i < 6; i++) cudaEventCreateWithFlags(&ev[i], cudaEventDisableTiming);
    }

    int g2E = ceil_div(2 * E, 256);
    const size_t WSZ = (size_t)HID * HID;

    // 0: weight transpose+split; 1: input projections
    prep_weights_kernel<<<16, 256>>>(n2c_wl, n2c_wr, c2n_wl, c2n_wr, wth, wtl);
    proj_both_kernel<<<NN + NC, 128>>>(x_node, npw, npb, xn, x_class, cpw, cpb, xc);

    // fork: xr = xc @ n2c_wr[0] on s1; xl = xn @ n2c_wl[0] on s0; CSR on s0
    cudaEventRecord(ev[0], 0);
    cudaStreamWaitEvent(s1, ev[0], 0);
    mm_gemm_p<<<GRIDP, 256, MM_SMEM, s1>>>(xc, wth + (1 * 4 + 0) * WSZ,
                                           wtl + (1 * 4 + 0) * WSZ, n2c_br, xr, NC);
    cudaEventRecord(ev[1], s1);
    mm_gemm_p<<<GRIDP, 256, MM_SMEM>>>(xn, wth + (0 * 4 + 0) * WSZ,
                                       wtl + (0 * 4 + 0) * WSZ, n2c_bl, xl, NN);
    build_zero_kernel<<<ceil_div(NN, 256), 256>>>(deg_m, deg_c);
    build_hist_kernel<<<g2E, 256>>>(member_dst, contains_dst, deg_m, deg_c, E);
    scanA_kernel<<<NB_T, 256>>>(deg_m, deg_c, part);
    scanB_kernel<<<1, 128>>>(part, off_m, off_c, E);
    scanC_kernel<<<NB_T, 256>>>(deg_m, deg_c, part, off_m, off_c, cur_m, cur_c);
    build_scatter_kernel<<<g2E, 256>>>(member_src, member_dst, contains_src, contains_dst,
                                       cur_m, cur_c, src_m, src_c, E);
    cudaStreamWaitEvent(0, ev[1], 0);  // join: xr ready

    for (int l = 0; l < NL; l++) {
        if (l < NL - 1) {
            // fork: xr2 = xn @ c2n_wr[l] (independent of gat_n2c)
            cudaEventRecord(ev[2], 0);
            cudaStreamWaitEvent(s1, ev[2], 0);
            mm_gemm_p<<<GRIDP, 256, MM_SMEM, s1>>>(xn, wth + (3 * 4 + l) * WSZ,
                                                   wtl + (3 * 4 + l) * WSZ,
                                                   c2n_br + l * HID, xr2, NN);
            cudaEventRecord(ev[3], s1);
        }
        gat_kernel<<<ceil_div(NC * 32, 256), 256>>>(off_m, src_m, xl, xr,
                                                    n2c_att + l * HID, n2c_bias + l * HID,
                                                    ln_cg + l * HID, ln_cb + l * HID,
                                                    xc, NC);
        if (l == NL - 1) break;  // layer-3 c2n is dead work (output depends only on xc)

        // fork: xr(next) = xc @ n2c_wr[l+1]  (needs updated xc; overlaps gat_c2n)
        cudaEventRecord(ev[4], 0);
        cudaStreamWaitEvent(s1, ev[4], 0);
        mm_gemm_p<<<GRIDP, 256, MM_SMEM, s1>>>(xc, wth + (1 * 4 + (l + 1)) * WSZ,
                                               wtl + (1 * 4 + (l + 1)) * WSZ,
                                               n2c_br + (l + 1) * HID, xr, NC);
        cudaEventRecord(ev[5], s1);

        // s0: xl2 = xc @ c2n_wl[l]
        mm_gemm_p<<<GRIDP, 256, MM_SMEM>>>(xc, wth + (2 * 4 + l) * WSZ,
                                           wtl + (2 * 4 + l) * WSZ,
                                           c2n_bl + l * HID, xl2, NC);
        cudaStreamWaitEvent(0, ev[3], 0);  // join: xr2 ready
        gat_kernel<<<ceil_div(NN * 32, 256), 256>>>(off_c, src_c, xl2, xr2,
                                                    c2n_att + l * HID, c2n_bias + l * HID,
                                                    ln_ng + l * HID, ln_nb + l * HID,
                                                    xn, NN);
        // s0: xl(next) = xn @ n2c_wl[l+1]
        mm_gemm_p<<<GRIDP, 256, MM_SMEM>>>(xn, wth + (0 * 4 + (l + 1)) * WSZ,
                                           wtl + (0 * 4 + (l + 1)) * WSZ,
                                           n2c_bl + (l + 1) * HID, xl, NN);
        cudaStreamWaitEvent(0, ev[5], 0);  // join: xr(next) ready
    }

    // final: out = mean over rows of xc
    zero_out_kernel<<<1, 128>>>(out);
    colmean_kernel<<<256, 128>>>(xc, out, NC);
}